// round 2
// baseline (speedup 1.0000x reference)
#include <cuda_runtime.h>
#include <math.h>

#define NT 2
#define NN 50000
#define NE 500000
#define NI 128
#define NO 128
#define NH 8
#define ND 16
#define PADL 129
#define CPAD 132

// ---------------- scratch (allocation-free: device globals) ----------------
__device__ __align__(16) float g_Wc [NT*384*NI];   // fused [q; ke_eff; ve_eff] weights per type
__device__ __align__(16) float g_bc [NT*384];
__device__ __align__(16) float g_q  [NT*NN*NO];
__device__ __align__(16) float g_ke [NT*NN*NO];
__device__ __align__(16) float g_ve [NT*NN*NO];
__device__ __align__(16) float g_ex [NT*NE*NH];
__device__ __align__(16) float g_den[NT*NN*NH];
__device__ __align__(16) float g_agg[NT*NN*NO];

// ---------------- kernel 1: build effective weights ----------------
// Wc[t] rows 0..127   = q_w[t]                      (bias q_b)
// Wc[t] rows 128..255 = a_rel[t]-folded k_w[t] * p_rel[t,h]/sqrt(D)
// Wc[t] rows 256..383 = m_rel[t]-folded v_w[t]
__global__ void prep_kernel(const float* __restrict__ kw, const float* __restrict__ kb,
                            const float* __restrict__ qw, const float* __restrict__ qb,
                            const float* __restrict__ vw, const float* __restrict__ vb,
                            const float* __restrict__ ar, const float* __restrict__ mr,
                            const float* __restrict__ pr) {
    int gid = blockIdx.x * 256 + threadIdx.x;
    if (gid >= NT * 384 * NI) return;
    int t   = gid / (384 * NI);
    int rem = gid % (384 * NI);
    int row = rem / NI;
    int i   = rem % NI;
    float w, b;
    if (row < 128) {
        w = qw[(t*NO + row)*NI + i];
        b = qb[t*NO + row];
    } else if (row < 256) {
        int r = row - 128, h = r >> 4, j = r & 15;
        float s = pr[t*NH + h] * 0.25f;  // p_rel / sqrt(16)
        float acc = 0.f, bacc = 0.f;
        #pragma unroll
        for (int d = 0; d < 16; d++) {
            float a = ar[((t*NH + h)*ND + d)*ND + j];
            acc  += kw[(t*NO + h*16 + d)*NI + i] * a;
            bacc += kb[t*NO + h*16 + d] * a;
        }
        w = acc * s; b = bacc * s;
    } else {
        int r = row - 256, h = r >> 4, j = r & 15;
        float acc = 0.f, bacc = 0.f;
        #pragma unroll
        for (int d = 0; d < 16; d++) {
            float m = mr[((t*NH + h)*ND + d)*ND + j];
            acc  += vw[(t*NO + h*16 + d)*NI + i] * m;
            bacc += vb[t*NO + h*16 + d] * m;
        }
        w = acc; b = bacc;
    }
    g_Wc[gid] = w;
    if (i == 0) g_bc[t*384 + row] = b;
}

// ---------------- kernel 2: zero denom + agg ----------------
__global__ void zero_kernel() {
    long idx = (long)blockIdx.x * blockDim.x + threadIdx.x;
    const long n4a = (long)NT*NN*NO/4;
    const long n4d = (long)NT*NN*NH/4;
    float4 z = make_float4(0.f, 0.f, 0.f, 0.f);
    if (idx < n4a)              ((float4*)g_agg)[idx]       = z;
    else if (idx < n4a + n4d)   ((float4*)g_den)[idx - n4a] = z;
}

// ---------------- kernel 3: fused projection GEMM ----------------
// C[t] = x[t] @ Wc[t]^T + bc[t]   (50000 x 384), routed to g_q / g_ke / g_ve
__global__ __launch_bounds__(256) void proj_gemm(const float* __restrict__ x) {
    extern __shared__ float sm[];
    float* Xs = sm;                 // [128][PADL]  row-major (k last)
    float* Ws = sm + 128 * PADL;    // [128][PADL]
    int t  = blockIdx.z;
    int cb = blockIdx.x;            // 0..2 -> q / ke / ve
    int rb = blockIdx.y;            // 0..390
    int tid = threadIdx.x;
    int rbase = rb * 128;
    const float* xg = x    + (size_t)t * NN * NI;
    const float* wg = g_Wc + ((size_t)t * 384 + cb * 128) * NI;

    #pragma unroll
    for (int c = 0; c < 16; c++) {
        int lin = c * 256 + tid;            // float4 index 0..4095
        int row = lin >> 5, kc = lin & 31;
        int gr = rbase + row;
        float4 v = (gr < NN) ? ((const float4*)xg)[(size_t)gr*32 + kc]
                             : make_float4(0.f,0.f,0.f,0.f);
        float* dx = Xs + row * PADL + kc * 4;
        dx[0]=v.x; dx[1]=v.y; dx[2]=v.z; dx[3]=v.w;
        float4 w = ((const float4*)wg)[row*32 + kc];
        float* dw = Ws + row * PADL + kc * 4;
        dw[0]=w.x; dw[1]=w.y; dw[2]=w.z; dw[3]=w.w;
    }
    __syncthreads();

    int tx = tid & 15, ty = tid >> 4;
    float acc[8][8];
    #pragma unroll
    for (int i = 0; i < 8; i++)
        #pragma unroll
        for (int j = 0; j < 8; j++) acc[i][j] = 0.f;

    #pragma unroll 4
    for (int k = 0; k < 128; k++) {
        float a[8], b[8];
        #pragma unroll
        for (int i = 0; i < 8; i++) a[i] = Xs[(ty + 16*i) * PADL + k];
        #pragma unroll
        for (int j = 0; j < 8; j++) b[j] = Ws[(tx + 16*j) * PADL + k];
        #pragma unroll
        for (int i = 0; i < 8; i++)
            #pragma unroll
            for (int j = 0; j < 8; j++) acc[i][j] += a[i] * b[j];
    }

    float* outb = (cb == 0) ? g_q : (cb == 1) ? g_ke : g_ve;
    outb += (size_t)t * NN * NO;
    const float* bias = g_bc + t*384 + cb*128;
    float bj[8];
    #pragma unroll
    for (int j = 0; j < 8; j++) bj[j] = bias[tx + 16*j];
    #pragma unroll
    for (int i = 0; i < 8; i++) {
        int gr = rbase + ty + 16*i;
        if (gr < NN) {
            #pragma unroll
            for (int j = 0; j < 8; j++)
                outb[(size_t)gr * NO + tx + 16*j] = acc[i][j] + bj[j];
        }
    }
}

// ---------------- kernel 4: attention logits + softmax denominator ----------------
// alpha already scaled (p_rel/sqrt(D) folded into ke). No max-subtraction: |alpha| < ~8.
__global__ void attn_kernel(const int* __restrict__ ei) {
    int e  = blockIdx.y;
    int dt = 1 - e;
    int tid = threadIdx.x;
    int idx = blockIdx.x * 32 + (tid >> 3);
    int h   = tid & 7;
    const int* srcp = ei + (size_t)e * 2 * NE;
    const int* dstp = srcp + NE;
    int src = srcp[idx], dst = dstp[idx];
    const float4* qr = (const float4*)(g_q  + ((size_t)dt*NN + dst) * NO) + h*4;
    const float4* kr = (const float4*)(g_ke + ((size_t)e *NN + src) * NO) + h*4;
    float dot = 0.f;
    #pragma unroll
    for (int ii = 0; ii < 4; ii++) {
        float4 a = qr[ii], b = kr[ii];
        dot += a.x*b.x + a.y*b.y + a.z*b.z + a.w*b.w;
    }
    float ex = __expf(dot);
    g_ex[((size_t)e*NE + idx)*NH + h] = ex;
    atomicAdd(&g_den[((size_t)dt*NN + dst)*NH + h], ex);
}

// ---------------- kernel 5: weighted message aggregation ----------------
__device__ __forceinline__ void red_add_v4(float* addr, float4 v) {
    asm volatile("red.global.add.v4.f32 [%0], {%1, %2, %3, %4};"
                 :: "l"(__cvta_generic_to_global(addr)),
                    "f"(v.x), "f"(v.y), "f"(v.z), "f"(v.w) : "memory");
}

__global__ void agg_kernel(const int* __restrict__ ei) {
    int e  = blockIdx.y;
    int dt = 1 - e;
    int w  = threadIdx.x >> 5;
    int l  = threadIdx.x & 31;
    int idx = blockIdx.x * 8 + w;
    const int* srcp = ei + (size_t)e * 2 * NE;
    const int* dstp = srcp + NE;
    int src = srcp[idx], dst = dstp[idx];
    int h = l >> 2;
    float ex  = g_ex[((size_t)e*NE + idx)*NH + h];
    float den = g_den[((size_t)dt*NN + dst)*NH + h];
    float wgt = ex / (den + 1e-16f);
    float4 v = ((const float4*)(g_ve + ((size_t)e*NN + src) * NO))[l];
    v.x *= wgt; v.y *= wgt; v.z *= wgt; v.w *= wgt;
    red_add_v4(g_agg + ((size_t)dt*NN + dst)*NO + l*4, v);
}

// ---------------- kernel 6: epilogue GEMM + skip + relu + LayerNorm ----------------
__global__ __launch_bounds__(256) void out_gemm(const float* __restrict__ x,
                                                const float* __restrict__ aw,
                                                const float* __restrict__ ab,
                                                const float* __restrict__ skp,
                                                const float* __restrict__ lng,
                                                const float* __restrict__ lnb,
                                                float* __restrict__ out) {
    extern __shared__ float sm[];
    float* As  = sm;                       // [128][PADL] gelu(agg) tile; reused as C
    float* Ws  = sm + 128 * PADL;          // [128][PADL]
    float* Xs2 = sm + 2 * 128 * PADL;      // [128][CPAD] x tile (skip path)
    float* mu_s = Xs2 + 128 * CPAD;        // [128]
    float* rs_s = mu_s + 128;              // [128]

    int t = blockIdx.y, rb = blockIdx.x, tid = threadIdx.x;
    int rbase = rb * 128;
    const float* ag = g_agg + (size_t)t * NN * NO;
    const float* wg = aw    + (size_t)t * NO * NO;
    const float* xg = x     + (size_t)t * NN * NO;

    #pragma unroll
    for (int c = 0; c < 16; c++) {
        int lin = c * 256 + tid;
        int row = lin >> 5, kc = lin & 31;
        int gr = rbase + row;
        float4 v  = (gr < NN) ? ((const float4*)ag)[(size_t)gr*32 + kc] : make_float4(0.f,0.f,0.f,0.f);
        // exact gelu
        v.x = 0.5f*v.x*(1.f+erff(v.x*0.70710678118f));
        v.y = 0.5f*v.y*(1.f+erff(v.y*0.70710678118f));
        v.z = 0.5f*v.z*(1.f+erff(v.z*0.70710678118f));
        v.w = 0.5f*v.w*(1.f+erff(v.w*0.70710678118f));
        float* da = As + row * PADL + kc * 4;
        da[0]=v.x; da[1]=v.y; da[2]=v.z; da[3]=v.w;
        float4 w = ((const float4*)wg)[row*32 + kc];
        float* dw = Ws + row * PADL + kc * 4;
        dw[0]=w.x; dw[1]=w.y; dw[2]=w.z; dw[3]=w.w;
        float4 xv = (gr < NN) ? ((const float4*)xg)[(size_t)gr*32 + kc] : make_float4(0.f,0.f,0.f,0.f);
        ((float4*)(Xs2 + row * CPAD))[kc] = xv;
    }
    __syncthreads();

    int tx = tid & 15, ty = tid >> 4;
    float acc[8][8];
    #pragma unroll
    for (int i = 0; i < 8; i++)
        #pragma unroll
        for (int j = 0; j < 8; j++) acc[i][j] = 0.f;
    #pragma unroll 4
    for (int k = 0; k < 128; k++) {
        float a[8], b[8];
        #pragma unroll
        for (int i = 0; i < 8; i++) a[i] = As[(ty + 16*i) * PADL + k];
        #pragma unroll
        for (int j = 0; j < 8; j++) b[j] = Ws[(tx + 16*j) * PADL + k];
        #pragma unroll
        for (int i = 0; i < 8; i++)
            #pragma unroll
            for (int j = 0; j < 8; j++) acc[i][j] += a[i] * b[j];
    }
    __syncthreads();   // done reading As; reuse as C

    const float* bias = ab + t * NO;
    float bj[8];
    #pragma unroll
    for (int j = 0; j < 8; j++) bj[j] = bias[tx + 16*j];
    float* Cs = As;
    #pragma unroll
    for (int i = 0; i < 8; i++)
        #pragma unroll
        for (int j = 0; j < 8; j++)
            Cs[(ty + 16*i) * PADL + tx + 16*j] = acc[i][j] + bj[j];
    __syncthreads();

    float beta = 1.f / (1.f + __expf(-skp[t]));
    if (tid < 128) {
        int gr = rbase + tid;
        if (gr < NN) {
            float sum = 0.f, sq = 0.f;
            for (int c = 0; c < 128; c++) {
                float o = beta * Cs[tid * PADL + c] + (1.f - beta) * Xs2[tid * CPAD + c];
                o = fmaxf(o, 0.f);
                Cs[tid * PADL + c] = o;
                sum += o; sq += o * o;
            }
            float mu = sum * (1.f / 128.f);
            float var = sq * (1.f / 128.f) - mu * mu;
            mu_s[tid] = mu;
            rs_s[tid] = rsqrtf(var + 1e-5f);
        }
    }
    __syncthreads();

    #pragma unroll
    for (int c = 0; c < 64; c++) {
        int lin = c * 256 + tid;          // 0..16383
        int row = lin >> 7, col = lin & 127;
        int gr = rbase + row;
        if (gr < NN) {
            float val = (Cs[row * PADL + col] - mu_s[row]) * rs_s[row] * lng[col] + lnb[col];
            out[((size_t)t * NN + gr) * NO + col] = val;
        }
    }
}

// ---------------- launch ----------------
extern "C" void kernel_launch(void* const* d_in, const int* in_sizes, int n_in,
                              void* d_out, int out_size) {
    const float* x   = (const float*)d_in[0];
    const float* kw  = (const float*)d_in[1];
    const float* kb  = (const float*)d_in[2];
    const float* qw  = (const float*)d_in[3];
    const float* qb  = (const float*)d_in[4];
    const float* vw  = (const float*)d_in[5];
    const float* vb  = (const float*)d_in[6];
    const float* aw  = (const float*)d_in[7];
    const float* ab  = (const float*)d_in[8];
    const float* skp = (const float*)d_in[9];
    const float* ar  = (const float*)d_in[10];
    const float* mr  = (const float*)d_in[11];
    const float* pr  = (const float*)d_in[12];
    const float* lng = (const float*)d_in[13];
    const float* lnb = (const float*)d_in[14];
    const int*   ei  = (const int*)d_in[15];
    float* out = (float*)d_out;

    const int proj_smem = 2 * 128 * PADL * 4;                        // 132096 B
    const int epi_smem  = (2 * 128 * PADL + 128 * CPAD + 256) * 4;   // 200704 B
    cudaFuncSetAttribute(proj_gemm, cudaFuncAttributeMaxDynamicSharedMemorySize, proj_smem);
    cudaFuncSetAttribute(out_gemm,  cudaFuncAttributeMaxDynamicSharedMemorySize, epi_smem);

    prep_kernel<<<384, 256>>>(kw, kb, qw, qb, vw, vb, ar, mr, pr);
    zero_kernel<<<13282, 256>>>();
    proj_gemm<<<dim3(3, 391, 2), 256, proj_smem>>>(x);
    attn_kernel<<<dim3(NE / 32, 2), 256>>>(ei);
    agg_kernel<<<dim3(NE / 8, 2), 256>>>(ei);
    out_gemm<<<dim3(391, 2), 256, epi_smem>>>(x, aw, ab, skp, lng, lnb, out);
}

// round 4
// speedup vs baseline: 1.4925x; 1.4925x over previous
#include <cuda_runtime.h>
#include <cuda_bf16.h>
#include <math.h>
#include <stdint.h>

#define NT 2
#define NN 50000
#define NE 500000
#define NI 128
#define NO 128
#define NH 8
#define ND 16

// ---------------- scratch (allocation-free: device globals) ----------------
__device__ __align__(16) float g_Wc [NT*384*NI];   // fused [q; ke_eff; ve_eff] weights per type
__device__ __align__(16) float g_bc [NT*384];
__device__ __align__(16) float g_q  [NT*NN*NO];
__device__ __align__(16) float g_ke [NT*NN*NO];
__device__ __align__(16) float g_ve [NT*NN*NO];
__device__ __align__(16) float g_ex [NT*NE*NH];
__device__ __align__(16) float g_den[NT*NN*NH];
__device__ __align__(16) float g_agg[NT*NN*NO];

// ---------------- smem layout for MMA kernels ----------------
// bf16 tiles, 128 rows x 128 cols, padded row stride 272 bytes (136 bf16)
#define STRB 272
#define OFF_AHI 0
#define OFF_ALO 34816
#define OFF_BHI 69632
#define OFF_BLO 104448
#define SM_TOTAL 139264
#define CSTR 133   // float stride for staged C (bank-conflict-free: gcd(133,32)=1... 133 mod 32 = 5)

__device__ __forceinline__ uint32_t smem_u32(const void* p) {
    uint32_t a;
    asm("{ .reg .u64 t; cvta.to.shared.u64 t, %1; cvt.u32.u64 %0, t; }" : "=r"(a) : "l"(p));
    return a;
}

__device__ __forceinline__ void ldsm_x4(uint32_t& r0, uint32_t& r1, uint32_t& r2, uint32_t& r3, uint32_t addr) {
    asm volatile("ldmatrix.sync.aligned.m8n8.x4.shared.b16 {%0,%1,%2,%3}, [%4];"
                 : "=r"(r0), "=r"(r1), "=r"(r2), "=r"(r3) : "r"(addr));
}
__device__ __forceinline__ void ldsm_x2(uint32_t& r0, uint32_t& r1, uint32_t addr) {
    asm volatile("ldmatrix.sync.aligned.m8n8.x2.shared.b16 {%0,%1}, [%2];"
                 : "=r"(r0), "=r"(r1) : "r"(addr));
}
__device__ __forceinline__ void mma16816(float& c0, float& c1, float& c2, float& c3,
                                         uint32_t a0, uint32_t a1, uint32_t a2, uint32_t a3,
                                         uint32_t b0, uint32_t b1) {
    asm volatile("mma.sync.aligned.m16n8k16.row.col.f32.bf16.bf16.f32 "
                 "{%0,%1,%2,%3}, {%4,%5,%6,%7}, {%8,%9}, {%0,%1,%2,%3};"
                 : "+f"(c0), "+f"(c1), "+f"(c2), "+f"(c3)
                 : "r"(a0), "r"(a1), "r"(a2), "r"(a3), "r"(b0), "r"(b1));
}

// split a float4 into bf16 hi/lo pairs and store 8B each into padded smem tiles
__device__ __forceinline__ void split_store(char* sm, int hi_off, int lo_off, int row, int col, float4 v) {
    __nv_bfloat16 h0 = __float2bfloat16(v.x), h1 = __float2bfloat16(v.y),
                  h2 = __float2bfloat16(v.z), h3 = __float2bfloat16(v.w);
    float l0 = v.x - __bfloat162float(h0), l1 = v.y - __bfloat162float(h1),
          l2 = v.z - __bfloat162float(h2), l3 = v.w - __bfloat162float(h3);
    __nv_bfloat162 ph0; ph0.x = h0; ph0.y = h1;
    __nv_bfloat162 ph1; ph1.x = h2; ph1.y = h3;
    __nv_bfloat162 pl0 = __floats2bfloat162_rn(l0, l1);
    __nv_bfloat162 pl1 = __floats2bfloat162_rn(l2, l3);
    int off = row * STRB + col * 2;
    *reinterpret_cast<uint2*>(sm + hi_off + off) =
        make_uint2(*reinterpret_cast<unsigned*>(&ph0), *reinterpret_cast<unsigned*>(&ph1));
    *reinterpret_cast<uint2*>(sm + lo_off + off) =
        make_uint2(*reinterpret_cast<unsigned*>(&pl0), *reinterpret_cast<unsigned*>(&pl1));
}

// ---------------- warp-tile MMA core: 3-pass bf16 split, acc[4][4][4] ----------------
// warp layout: wm = wid&1 (2 x 64 rows), wn = wid>>1 (4 x 32 cols)
struct AccTile { float a[4][4][4]; };

__device__ __forceinline__ void mma_tile_compute(AccTile& T, uint32_t smb, int wid, int lane) {
    int wm = wid & 1, wn = wid >> 1;
    #pragma unroll
    for (int mt = 0; mt < 4; mt++)
        #pragma unroll
        for (int nt = 0; nt < 4; nt++)
            #pragma unroll
            for (int k = 0; k < 4; k++) T.a[mt][nt][k] = 0.f;

    // ldmatrix address bases
    uint32_t a_base[4], b_base[4];
    {
        int arow = wm * 64 + (lane & 15);
        int acol = ((lane >> 4) << 3);          // 0 or 8 (bf16 cols)
        #pragma unroll
        for (int mt = 0; mt < 4; mt++)
            a_base[mt] = smb + (arow + mt * 16) * STRB + acol * 2;
        int brow = wn * 32 + (lane & 7);
        int bcol = (lane & 8);                  // 0 or 8
        #pragma unroll
        for (int nt = 0; nt < 4; nt++)
            b_base[nt] = smb + (brow + nt * 8) * STRB + bcol * 2;
    }

    const int pa[3] = {OFF_AHI, OFF_AHI, OFF_ALO};
    const int pb[3] = {OFF_BHI, OFF_BLO, OFF_BHI};
    #pragma unroll
    for (int p = 0; p < 3; p++) {
        #pragma unroll
        for (int kt = 0; kt < 8; kt++) {
            uint32_t af[4][4], bf[4][2];
            #pragma unroll
            for (int mt = 0; mt < 4; mt++)
                ldsm_x4(af[mt][0], af[mt][1], af[mt][2], af[mt][3],
                        a_base[mt] + pa[p] + kt * 32);
            #pragma unroll
            for (int nt = 0; nt < 4; nt++)
                ldsm_x2(bf[nt][0], bf[nt][1], b_base[nt] + pb[p] + kt * 32);
            #pragma unroll
            for (int mt = 0; mt < 4; mt++)
                #pragma unroll
                for (int nt = 0; nt < 4; nt++)
                    mma16816(T.a[mt][nt][0], T.a[mt][nt][1], T.a[mt][nt][2], T.a[mt][nt][3],
                             af[mt][0], af[mt][1], af[mt][2], af[mt][3],
                             bf[nt][0], bf[nt][1]);
        }
    }
}

// ---------------- kernel 1: build effective weights ----------------
__global__ void prep_kernel(const float* __restrict__ kw, const float* __restrict__ kb,
                            const float* __restrict__ qw, const float* __restrict__ qb,
                            const float* __restrict__ vw, const float* __restrict__ vb,
                            const float* __restrict__ ar, const float* __restrict__ mr,
                            const float* __restrict__ pr) {
    int gid = blockIdx.x * 256 + threadIdx.x;
    if (gid >= NT * 384 * NI) return;
    int t   = gid / (384 * NI);
    int rem = gid % (384 * NI);
    int row = rem / NI;
    int i   = rem % NI;
    float w, b;
    if (row < 128) {
        w = qw[(t*NO + row)*NI + i];
        b = qb[t*NO + row];
    } else if (row < 256) {
        int r = row - 128, h = r >> 4, j = r & 15;
        float s = pr[t*NH + h] * 0.25f;
        float acc = 0.f, bacc = 0.f;
        #pragma unroll
        for (int d = 0; d < 16; d++) {
            float a = ar[((t*NH + h)*ND + d)*ND + j];
            acc  += kw[(t*NO + h*16 + d)*NI + i] * a;
            bacc += kb[t*NO + h*16 + d] * a;
        }
        w = acc * s; b = bacc * s;
    } else {
        int r = row - 256, h = r >> 4, j = r & 15;
        float acc = 0.f, bacc = 0.f;
        #pragma unroll
        for (int d = 0; d < 16; d++) {
            float m = mr[((t*NH + h)*ND + d)*ND + j];
            acc  += vw[(t*NO + h*16 + d)*NI + i] * m;
            bacc += vb[t*NO + h*16 + d] * m;
        }
        w = acc; b = bacc;
    }
    g_Wc[gid] = w;
    if (i == 0) g_bc[t*384 + row] = b;
}

// ---------------- kernel 2: zero denom + agg ----------------
__global__ void zero_kernel() {
    long idx = (long)blockIdx.x * blockDim.x + threadIdx.x;
    const long n4a = (long)NT*NN*NO/4;
    const long n4d = (long)NT*NN*NH/4;
    float4 z = make_float4(0.f, 0.f, 0.f, 0.f);
    if (idx < n4a)              ((float4*)g_agg)[idx]       = z;
    else if (idx < n4a + n4d)   ((float4*)g_den)[idx - n4a] = z;
}

// ---------------- kernel 3: projection GEMM (mma.sync bf16 split) ----------------
__global__ __launch_bounds__(256, 1) void proj_mma(const float* __restrict__ x) {
    extern __shared__ char sm[];
    uint32_t smb = smem_u32(sm);
    int tid = threadIdx.x, wid = tid >> 5, lane = tid & 31;
    int cb = blockIdx.x, rb = blockIdx.y, t = blockIdx.z;
    int rbase = rb * 128;

    const float* xg = x    + (size_t)t * NN * NI;
    const float* wg = g_Wc + ((size_t)t * 384 + cb * 128) * NI;

    #pragma unroll 4
    for (int it = 0; it < 16; it++) {
        int lin = it * 256 + tid;
        int row = lin >> 5, col = (lin & 31) * 4;
        int gr = rbase + row;
        float4 v = (gr < NN) ? __ldg((const float4*)(xg + (size_t)gr * 128 + col))
                             : make_float4(0.f, 0.f, 0.f, 0.f);
        split_store(sm, OFF_AHI, OFF_ALO, row, col, v);
        float4 w = __ldg((const float4*)(wg + row * 128 + col));
        split_store(sm, OFF_BHI, OFF_BLO, row, col, w);
    }
    __syncthreads();

    AccTile T;
    mma_tile_compute(T, smb, wid, lane);

    // direct stores with bias
    float* outb = (cb == 0) ? g_q : (cb == 1) ? g_ke : g_ve;
    outb += (size_t)t * NN * NO;
    const float* bias = g_bc + t * 384 + cb * 128;
    int wm = wid & 1, wn = wid >> 1;
    int g = lane >> 2, tig = lane & 3;
    float2 bfr[4];
    #pragma unroll
    for (int nt = 0; nt < 4; nt++)
        bfr[nt] = *(const float2*)(bias + wn * 32 + nt * 8 + tig * 2);
    #pragma unroll
    for (int mt = 0; mt < 4; mt++) {
        int r0 = rbase + wm * 64 + mt * 16 + g;
        #pragma unroll
        for (int nt = 0; nt < 4; nt++) {
            int col = wn * 32 + nt * 8 + tig * 2;
            if (r0 < NN)
                *(float2*)(outb + (size_t)r0 * 128 + col) =
                    make_float2(T.a[mt][nt][0] + bfr[nt].x, T.a[mt][nt][1] + bfr[nt].y);
            if (r0 + 8 < NN)
                *(float2*)(outb + (size_t)(r0 + 8) * 128 + col) =
                    make_float2(T.a[mt][nt][2] + bfr[nt].x, T.a[mt][nt][3] + bfr[nt].y);
        }
    }
}

// ---------------- kernel 4: attention logits + softmax denom (coalesced) ----------------
__global__ void attn_kernel(const int* __restrict__ ei) {
    int e = blockIdx.y, dt = 1 - e;
    int tid = threadIdx.x;
    int warp = tid >> 5, lane = tid & 31;
    int g = lane >> 3, j = lane & 7;
    int idx = blockIdx.x * 32 + warp * 4 + g;
    const int* srcp = ei + (size_t)e * 2 * NE;
    int src = srcp[idx], dst = srcp[NE + idx];
    const float4* qr = (const float4*)(g_q  + ((size_t)dt * NN + dst) * NO);
    const float4* kr = (const float4*)(g_ke + ((size_t)e  * NN + src) * NO);
    float part[4];
    #pragma unroll
    for (int c = 0; c < 4; c++) {
        float4 a = qr[c * 8 + j], b = kr[c * 8 + j];
        part[c] = a.x*b.x + a.y*b.y + a.z*b.z + a.w*b.w;
    }
    #pragma unroll
    for (int c = 0; c < 4; c++) {
        float v = part[c];
        v += __shfl_xor_sync(0xffffffffu, v, 1);
        v += __shfl_xor_sync(0xffffffffu, v, 2);
        if ((j & 3) == 0) {
            int h = c * 2 + (j >> 2);
            float ex = __expf(v);
            g_ex[((size_t)e * NE + idx) * NH + h] = ex;
            atomicAdd(&g_den[((size_t)dt * NN + dst) * NH + h], ex);
        }
    }
}

// ---------------- kernel 5: weighted message aggregation ----------------
__device__ __forceinline__ void red_add_v4(float* addr, float4 v) {
    asm volatile("red.global.add.v4.f32 [%0], {%1, %2, %3, %4};"
                 :: "l"(__cvta_generic_to_global(addr)),
                    "f"(v.x), "f"(v.y), "f"(v.z), "f"(v.w) : "memory");
}

__global__ void agg_kernel(const int* __restrict__ ei) {
    int e  = blockIdx.y, dt = 1 - e;
    int w  = threadIdx.x >> 5, l = threadIdx.x & 31;
    int idx = blockIdx.x * 8 + w;
    const int* srcp = ei + (size_t)e * 2 * NE;
    int src = srcp[idx], dst = srcp[NE + idx];
    int h = l >> 2;
    float ex  = g_ex[((size_t)e * NE + idx) * NH + h];
    float den = g_den[((size_t)dt * NN + dst) * NH + h];
    float wgt = ex / (den + 1e-16f);
    float4 v = ((const float4*)(g_ve + ((size_t)e * NN + src) * NO))[l];
    v.x *= wgt; v.y *= wgt; v.z *= wgt; v.w *= wgt;
    red_add_v4(g_agg + ((size_t)dt * NN + dst) * NO + l * 4, v);
}

// ---------------- kernel 6: epilogue GEMM + skip + relu + LayerNorm ----------------
__global__ __launch_bounds__(256, 1) void out_mma(const float* __restrict__ x,
                                                  const float* __restrict__ aw,
                                                  const float* __restrict__ ab,
                                                  const float* __restrict__ skp,
                                                  const float* __restrict__ lng,
                                                  const float* __restrict__ lnb,
                                                  float* __restrict__ out) {
    extern __shared__ char sm[];
    uint32_t smb = smem_u32(sm);
    int tid = threadIdx.x, wid = tid >> 5, lane = tid & 31;
    int rb = blockIdx.x, t = blockIdx.y;
    int rbase = rb * 128;

    const float* ag = g_agg + (size_t)t * NN * NO;
    const float* wg = aw    + (size_t)t * NO * NO;

    #pragma unroll 4
    for (int it = 0; it < 16; it++) {
        int lin = it * 256 + tid;
        int row = lin >> 5, col = (lin & 31) * 4;
        int gr = rbase + row;
        float4 v = (gr < NN) ? __ldg((const float4*)(ag + (size_t)gr * 128 + col))
                             : make_float4(0.f, 0.f, 0.f, 0.f);
        v.x = 0.5f * v.x * (1.f + erff(v.x * 0.70710678118f));
        v.y = 0.5f * v.y * (1.f + erff(v.y * 0.70710678118f));
        v.z = 0.5f * v.z * (1.f + erff(v.z * 0.70710678118f));
        v.w = 0.5f * v.w * (1.f + erff(v.w * 0.70710678118f));
        split_store(sm, OFF_AHI, OFF_ALO, row, col, v);
        float4 w = __ldg((const float4*)(wg + row * 128 + col));
        split_store(sm, OFF_BHI, OFF_BLO, row, col, w);
    }
    __syncthreads();

    AccTile T;
    mma_tile_compute(T, smb, wid, lane);
    __syncthreads();   // done with bf16 tiles; reuse smem for C staging

    // stage C (+bias) into smem rows, stride CSTR floats
    float* Cs = (float*)sm;
    {
        const float* bias = ab + t * 128;
        int wm = wid & 1, wn = wid >> 1;
        int g = lane >> 2, tig = lane & 3;
        float2 bfr[4];
        #pragma unroll
        for (int nt = 0; nt < 4; nt++)
            bfr[nt] = *(const float2*)(bias + wn * 32 + nt * 8 + tig * 2);
        #pragma unroll
        for (int mt = 0; mt < 4; mt++) {
            int r0 = wm * 64 + mt * 16 + g;
            #pragma unroll
            for (int nt = 0; nt < 4; nt++) {
                int col = wn * 32 + nt * 8 + tig * 2;
                Cs[r0 * CSTR + col]           = T.a[mt][nt][0] + bfr[nt].x;
                Cs[r0 * CSTR + col + 1]       = T.a[mt][nt][1] + bfr[nt].y;
                Cs[(r0 + 8) * CSTR + col]     = T.a[mt][nt][2] + bfr[nt].x;
                Cs[(r0 + 8) * CSTR + col + 1] = T.a[mt][nt][3] + bfr[nt].y;
            }
        }
    }
    __syncthreads();

    // per-row skip + relu + LayerNorm, fully in registers
    if (tid < 128) {
        int gr = rbase + tid;
        if (gr < NN) {
            float r[128];
            #pragma unroll
            for (int c = 0; c < 128; c++) r[c] = Cs[tid * CSTR + c];
            float beta = 1.f / (1.f + __expf(-skp[t]));
            const float* xr = x + ((size_t)t * NN + gr) * 128;
            float sum = 0.f, sq = 0.f;
            #pragma unroll
            for (int c4 = 0; c4 < 32; c4++) {
                float4 xv = __ldg((const float4*)(xr + c4 * 4));
                float o0 = fmaxf(beta * r[c4*4+0] + (1.f - beta) * xv.x, 0.f);
                float o1 = fmaxf(beta * r[c4*4+1] + (1.f - beta) * xv.y, 0.f);
                float o2 = fmaxf(beta * r[c4*4+2] + (1.f - beta) * xv.z, 0.f);
                float o3 = fmaxf(beta * r[c4*4+3] + (1.f - beta) * xv.w, 0.f);
                r[c4*4+0] = o0; r[c4*4+1] = o1; r[c4*4+2] = o2; r[c4*4+3] = o3;
                sum += o0 + o1 + o2 + o3;
                sq  += o0*o0 + o1*o1 + o2*o2 + o3*o3;
            }
            float mu  = sum * (1.f / 128.f);
            float var = sq * (1.f / 128.f) - mu * mu;
            float rs  = rsqrtf(var + 1e-5f);
            float* op = out + ((size_t)t * NN + gr) * 128;
            #pragma unroll
            for (int c4 = 0; c4 < 32; c4++) {
                float4 gv = *(const float4*)(lng + c4 * 4);
                float4 bv = *(const float4*)(lnb + c4 * 4);
                float4 o;
                o.x = (r[c4*4+0] - mu) * rs * gv.x + bv.x;
                o.y = (r[c4*4+1] - mu) * rs * gv.y + bv.y;
                o.z = (r[c4*4+2] - mu) * rs * gv.z + bv.z;
                o.w = (r[c4*4+3] - mu) * rs * gv.w + bv.w;
                *(float4*)(op + c4 * 4) = o;
            }
        }
    }
}

// ---------------- launch ----------------
extern "C" void kernel_launch(void* const* d_in, const int* in_sizes, int n_in,
                              void* d_out, int out_size) {
    const float* x   = (const float*)d_in[0];
    const float* kw  = (const float*)d_in[1];
    const float* kb  = (const float*)d_in[2];
    const float* qw  = (const float*)d_in[3];
    const float* qb  = (const float*)d_in[4];
    const float* vw  = (const float*)d_in[5];
    const float* vb  = (const float*)d_in[6];
    const float* aw  = (const float*)d_in[7];
    const float* ab  = (const float*)d_in[8];
    const float* skp = (const float*)d_in[9];
    const float* ar  = (const float*)d_in[10];
    const float* mr  = (const float*)d_in[11];
    const float* pr  = (const float*)d_in[12];
    const float* lng = (const float*)d_in[13];
    const float* lnb = (const float*)d_in[14];
    const int*   ei  = (const int*)d_in[15];
    float* out = (float*)d_out;

    cudaFuncSetAttribute(proj_mma, cudaFuncAttributeMaxDynamicSharedMemorySize, SM_TOTAL);
    cudaFuncSetAttribute(out_mma,  cudaFuncAttributeMaxDynamicSharedMemorySize, SM_TOTAL);

    prep_kernel<<<384, 256>>>(kw, kb, qw, qb, vw, vb, ar, mr, pr);
    zero_kernel<<<13282, 256>>>();
    proj_mma<<<dim3(3, 391, 2), 256, SM_TOTAL>>>(x);
    attn_kernel<<<dim3(NE / 32, 2), 256>>>(ei);
    agg_kernel<<<dim3(NE / 8, 2), 256>>>(ei);
    out_mma<<<dim3(391, 2), 256, SM_TOTAL>>>(x, aw, ab, skp, lng, lnb, out);
}

// round 8
// speedup vs baseline: 1.7563x; 1.1768x over previous
#include <cuda_runtime.h>
#include <cuda_bf16.h>
#include <math.h>
#include <stdint.h>

#define NT 2
#define NN 50000
#define NE 500000
#define NI 128
#define NO 128
#define NH 8
#define ND 16

// ---------------- scratch (allocation-free: device globals) ----------------
__device__ __align__(16) float g_Wc [NT*384*NI];
__device__ __align__(16) float g_bc [NT*384];
__device__ __align__(16) float g_q  [NT*NN*NO];
__device__ __align__(16) float g_ke [NT*NN*NO];
__device__ __align__(16) float g_ve [NT*NN*NO];
__device__ __align__(16) float g_agg[NT*NN*NO];
__device__ __align__(16) float g_exc[2ll*NE*NH];     // ex per (relation, csr-pos, head)
__device__ __align__(16) int   g_cnt[2*NN];
__device__ __align__(16) int   g_cur[2*NN];
__device__ __align__(16) int   g_off[2*(NN+1)];
__device__ __align__(16) int   g_csr[2*NE];          // src indices grouped by dst

// ---------------- smem layout for MMA kernels ----------------
#define STRB 272
#define OFF_AHI 0
#define OFF_ALO 34816
#define OFF_BHI 69632
#define OFF_BLO 104448
#define SM_TOTAL 139264
#define CSTR 133

__device__ __forceinline__ uint32_t smem_u32(const void* p) {
    uint32_t a;
    asm("{ .reg .u64 t; cvta.to.shared.u64 t, %1; cvt.u32.u64 %0, t; }" : "=r"(a) : "l"(p));
    return a;
}
__device__ __forceinline__ void ldsm_x4(uint32_t& r0, uint32_t& r1, uint32_t& r2, uint32_t& r3, uint32_t addr) {
    asm volatile("ldmatrix.sync.aligned.m8n8.x4.shared.b16 {%0,%1,%2,%3}, [%4];"
                 : "=r"(r0), "=r"(r1), "=r"(r2), "=r"(r3) : "r"(addr));
}
__device__ __forceinline__ void ldsm_x2(uint32_t& r0, uint32_t& r1, uint32_t addr) {
    asm volatile("ldmatrix.sync.aligned.m8n8.x2.shared.b16 {%0,%1}, [%2];"
                 : "=r"(r0), "=r"(r1) : "r"(addr));
}
__device__ __forceinline__ void mma16816(float& c0, float& c1, float& c2, float& c3,
                                         uint32_t a0, uint32_t a1, uint32_t a2, uint32_t a3,
                                         uint32_t b0, uint32_t b1) {
    asm volatile("mma.sync.aligned.m16n8k16.row.col.f32.bf16.bf16.f32 "
                 "{%0,%1,%2,%3}, {%4,%5,%6,%7}, {%8,%9}, {%0,%1,%2,%3};"
                 : "+f"(c0), "+f"(c1), "+f"(c2), "+f"(c3)
                 : "r"(a0), "r"(a1), "r"(a2), "r"(a3), "r"(b0), "r"(b1));
}

__device__ __forceinline__ void split_store(char* sm, int hi_off, int lo_off, int row, int col, float4 v) {
    __nv_bfloat16 h0 = __float2bfloat16(v.x), h1 = __float2bfloat16(v.y),
                  h2 = __float2bfloat16(v.z), h3 = __float2bfloat16(v.w);
    float l0 = v.x - __bfloat162float(h0), l1 = v.y - __bfloat162float(h1),
          l2 = v.z - __bfloat162float(h2), l3 = v.w - __bfloat162float(h3);
    __nv_bfloat162 ph0; ph0.x = h0; ph0.y = h1;
    __nv_bfloat162 ph1; ph1.x = h2; ph1.y = h3;
    __nv_bfloat162 pl0 = __floats2bfloat162_rn(l0, l1);
    __nv_bfloat162 pl1 = __floats2bfloat162_rn(l2, l3);
    int off = row * STRB + col * 2;
    *reinterpret_cast<uint2*>(sm + hi_off + off) =
        make_uint2(*reinterpret_cast<unsigned*>(&ph0), *reinterpret_cast<unsigned*>(&ph1));
    *reinterpret_cast<uint2*>(sm + lo_off + off) =
        make_uint2(*reinterpret_cast<unsigned*>(&pl0), *reinterpret_cast<unsigned*>(&pl1));
}

struct AccTile { float a[4][4][4]; };

__device__ __forceinline__ void mma_tile_compute(AccTile& T, uint32_t smb, int wid, int lane) {
    int wm = wid & 1, wn = wid >> 1;
    #pragma unroll
    for (int mt = 0; mt < 4; mt++)
        #pragma unroll
        for (int nt = 0; nt < 4; nt++)
            #pragma unroll
            for (int k = 0; k < 4; k++) T.a[mt][nt][k] = 0.f;

    uint32_t a_base[4], b_base[4];
    {
        int arow = wm * 64 + (lane & 15);
        int acol = ((lane >> 4) << 3);
        #pragma unroll
        for (int mt = 0; mt < 4; mt++)
            a_base[mt] = smb + (arow + mt * 16) * STRB + acol * 2;
        int brow = wn * 32 + (lane & 7);
        int bcol = (lane & 8);
        #pragma unroll
        for (int nt = 0; nt < 4; nt++)
            b_base[nt] = smb + (brow + nt * 8) * STRB + bcol * 2;
    }

    const int pa[3] = {OFF_AHI, OFF_AHI, OFF_ALO};
    const int pb[3] = {OFF_BHI, OFF_BLO, OFF_BHI};
    #pragma unroll
    for (int p = 0; p < 3; p++) {
        #pragma unroll
        for (int kt = 0; kt < 8; kt++) {
            uint32_t af[4][4], bf[4][2];
            #pragma unroll
            for (int mt = 0; mt < 4; mt++)
                ldsm_x4(af[mt][0], af[mt][1], af[mt][2], af[mt][3],
                        a_base[mt] + pa[p] + kt * 32);
            #pragma unroll
            for (int nt = 0; nt < 4; nt++)
                ldsm_x2(bf[nt][0], bf[nt][1], b_base[nt] + pb[p] + kt * 32);
            #pragma unroll
            for (int mt = 0; mt < 4; mt++)
                #pragma unroll
                for (int nt = 0; nt < 4; nt++)
                    mma16816(T.a[mt][nt][0], T.a[mt][nt][1], T.a[mt][nt][2], T.a[mt][nt][3],
                             af[mt][0], af[mt][1], af[mt][2], af[mt][3],
                             bf[nt][0], bf[nt][1]);
        }
    }
}

// ---------------- kernel 1: build effective weights ----------------
__global__ void prep_kernel(const float* __restrict__ kw, const float* __restrict__ kb,
                            const float* __restrict__ qw, const float* __restrict__ qb,
                            const float* __restrict__ vw, const float* __restrict__ vb,
                            const float* __restrict__ ar, const float* __restrict__ mr,
                            const float* __restrict__ pr) {
    int gid = blockIdx.x * 256 + threadIdx.x;
    if (gid >= NT * 384 * NI) return;
    int t   = gid / (384 * NI);
    int rem = gid % (384 * NI);
    int row = rem / NI;
    int i   = rem % NI;
    float w, b;
    if (row < 128) {
        w = qw[(t*NO + row)*NI + i];
        b = qb[t*NO + row];
    } else if (row < 256) {
        int r = row - 128, h = r >> 4, j = r & 15;
        float s = pr[t*NH + h] * 0.25f;
        float acc = 0.f, bacc = 0.f;
        #pragma unroll
        for (int d = 0; d < 16; d++) {
            float a = ar[((t*NH + h)*ND + d)*ND + j];
            acc  += kw[(t*NO + h*16 + d)*NI + i] * a;
            bacc += kb[t*NO + h*16 + d] * a;
        }
        w = acc * s; b = bacc * s;
    } else {
        int r = row - 256, h = r >> 4, j = r & 15;
        float acc = 0.f, bacc = 0.f;
        #pragma unroll
        for (int d = 0; d < 16; d++) {
            float m = mr[((t*NH + h)*ND + d)*ND + j];
            acc  += vw[(t*NO + h*16 + d)*NI + i] * m;
            bacc += vb[t*NO + h*16 + d] * m;
        }
        w = acc; b = bacc;
    }
    g_Wc[gid] = w;
    if (i == 0) g_bc[t*384 + row] = b;
}

// ---------------- CSR build ----------------
__global__ void csr_zero() {
    int i = blockIdx.x * 1024 + threadIdx.x;
    if (i < 2 * NN) { g_cnt[i] = 0; g_cur[i] = 0; }
}

__global__ void csr_count(const int* __restrict__ ei) {
    int e = blockIdx.y;
    int idx = blockIdx.x * 256 + threadIdx.x;
    if (idx >= NE) return;
    int dst = ei[(size_t)e * 2 * NE + NE + idx];
    atomicAdd(&g_cnt[e * NN + dst], 1);
}

__global__ void csr_scan() {   // grid = 2 blocks, 1024 threads
    int e = blockIdx.x;
    const int* cnt = g_cnt + e * NN;
    int* off = g_off + e * (NN + 1);
    int tid = threadIdx.x;
    const int PER = 49;                  // 1024*49 >= 50000
    int base = tid * PER;
    int s = 0;
    #pragma unroll
    for (int i = 0; i < PER; i++) {
        int idx = base + i;
        if (idx < NN) s += cnt[idx];
    }
    __shared__ int sm[1024];
    sm[tid] = s;
    __syncthreads();
    for (int d = 1; d < 1024; d <<= 1) {
        int v = (tid >= d) ? sm[tid - d] : 0;
        __syncthreads();
        sm[tid] += v;
        __syncthreads();
    }
    int run = sm[tid] - s;               // exclusive prefix
    #pragma unroll
    for (int i = 0; i < PER; i++) {
        int idx = base + i;
        if (idx < NN) { off[idx] = run; run += cnt[idx]; }
    }
    if (tid == 1023) off[NN] = run;
}

__global__ void csr_scatter(const int* __restrict__ ei) {
    int e = blockIdx.y;
    int idx = blockIdx.x * 256 + threadIdx.x;
    if (idx >= NE) return;
    const int* srcp = ei + (size_t)e * 2 * NE;
    int src = srcp[idx], dst = srcp[NE + idx];
    int pos = atomicAdd(&g_cur[e * NN + dst], 1);
    g_csr[e * NE + g_off[e * (NN + 1) + dst] + pos] = src;
}

// ---------------- kernel 3: projection GEMM (mma.sync bf16 split) ----------------
__global__ __launch_bounds__(256, 1) void proj_mma(const float* __restrict__ x) {
    extern __shared__ char sm[];
    uint32_t smb = smem_u32(sm);
    int tid = threadIdx.x, wid = tid >> 5, lane = tid & 31;
    int cb = blockIdx.x, rb = blockIdx.y, t = blockIdx.z;
    int rbase = rb * 128;

    const float* xg = x    + (size_t)t * NN * NI;
    const float* wg = g_Wc + ((size_t)t * 384 + cb * 128) * NI;

    #pragma unroll 4
    for (int it = 0; it < 16; it++) {
        int lin = it * 256 + tid;
        int row = lin >> 5, col = (lin & 31) * 4;
        int gr = rbase + row;
        float4 v = (gr < NN) ? __ldg((const float4*)(xg + (size_t)gr * 128 + col))
                             : make_float4(0.f, 0.f, 0.f, 0.f);
        split_store(sm, OFF_AHI, OFF_ALO, row, col, v);
        float4 w = __ldg((const float4*)(wg + row * 128 + col));
        split_store(sm, OFF_BHI, OFF_BLO, row, col, w);
    }
    __syncthreads();

    AccTile T;
    mma_tile_compute(T, smb, wid, lane);

    float* outb = (cb == 0) ? g_q : (cb == 1) ? g_ke : g_ve;
    outb += (size_t)t * NN * NO;
    const float* bias = g_bc + t * 384 + cb * 128;
    int wm = wid & 1, wn = wid >> 1;
    int g = lane >> 2, tig = lane & 3;
    float2 bfr[4];
    #pragma unroll
    for (int nt = 0; nt < 4; nt++)
        bfr[nt] = *(const float2*)(bias + wn * 32 + nt * 8 + tig * 2);
    #pragma unroll
    for (int mt = 0; mt < 4; mt++) {
        int r0 = rbase + wm * 64 + mt * 16 + g;
        #pragma unroll
        for (int nt = 0; nt < 4; nt++) {
            int col = wn * 32 + nt * 8 + tig * 2;
            if (r0 < NN)
                *(float2*)(outb + (size_t)r0 * 128 + col) =
                    make_float2(T.a[mt][nt][0] + bfr[nt].x, T.a[mt][nt][1] + bfr[nt].y);
            if (r0 + 8 < NN)
                *(float2*)(outb + (size_t)(r0 + 8) * 128 + col) =
                    make_float2(T.a[mt][nt][2] + bfr[nt].x, T.a[mt][nt][3] + bfr[nt].y);
        }
    }
}

// ---------------- kernel 4: fused attention + aggregation (warp per dst node) ----------------
__global__ __launch_bounds__(256) void edge_fused() {
    int e  = blockIdx.y, dt = 1 - e;
    int wid = threadIdx.x >> 5, lane = threadIdx.x & 31;
    int node = blockIdx.x * 8 + wid;
    // node < NN guaranteed: grid.x = NN/8 = 6250 exact

    // q row: lane holds floats [lane*4, lane*4+4); quad = head
    float4 qv = ((const float4*)(g_q + ((size_t)dt * NN + node) * NO))[lane];
    int j0 = g_off[e * (NN + 1) + node];
    int j1 = g_off[e * (NN + 1) + node + 1];
    int quad = lane >> 2, ql = lane & 3;

    const int*   csr = g_csr + (size_t)e * NE;
    const float* keb = g_ke + (size_t)e * NN * NO;
    const float* veb = g_ve + (size_t)e * NN * NO;
    float*       exb = g_exc + (size_t)e * NE * NH;

    float den = 0.f;
    for (int j = j0; j < j1; j++) {
        int src = csr[j];
        float4 kv = ((const float4*)(keb + (size_t)src * NO))[lane];
        float d = qv.x * kv.x + qv.y * kv.y + qv.z * kv.z + qv.w * kv.w;
        d += __shfl_xor_sync(0xffffffffu, d, 1);
        d += __shfl_xor_sync(0xffffffffu, d, 2);
        float ex = __expf(d);
        den += ex;
        if (ql == 0) exb[(size_t)j * NH + quad] = ex;
    }
    float inv = 1.f / (den + 1e-16f);

    float4 acc = make_float4(0.f, 0.f, 0.f, 0.f);
    for (int j = j0; j < j1; j++) {
        int src = csr[j];
        float ex = exb[(size_t)j * NH + quad];
        float4 vv = ((const float4*)(veb + (size_t)src * NO))[lane];
        acc.x += vv.x * ex; acc.y += vv.y * ex;
        acc.z += vv.z * ex; acc.w += vv.w * ex;
    }
    acc.x *= inv; acc.y *= inv; acc.z *= inv; acc.w *= inv;
    // relations write disjoint dst types -> plain store, no zero-init needed
    ((float4*)(g_agg + ((size_t)dt * NN + node) * NO))[lane] = acc;
}

// ---------------- kernel 5: epilogue GEMM + skip + relu + LayerNorm ----------------
__global__ __launch_bounds__(256, 1) void out_mma(const float* __restrict__ x,
                                                  const float* __restrict__ aw,
                                                  const float* __restrict__ ab,
                                                  const float* __restrict__ skp,
                                                  const float* __restrict__ lng,
                                                  const float* __restrict__ lnb,
                                                  float* __restrict__ out) {
    extern __shared__ char sm[];
    uint32_t smb = smem_u32(sm);
    int tid = threadIdx.x, wid = tid >> 5, lane = tid & 31;
    int rb = blockIdx.x, t = blockIdx.y;
    int rbase = rb * 128;

    const float* ag = g_agg + (size_t)t * NN * NO;
    const float* wg = aw    + (size_t)t * NO * NO;

    #pragma unroll 4
    for (int it = 0; it < 16; it++) {
        int lin = it * 256 + tid;
        int row = lin >> 5, col = (lin & 31) * 4;
        int gr = rbase + row;
        float4 v = (gr < NN) ? __ldg((const float4*)(ag + (size_t)gr * 128 + col))
                             : make_float4(0.f, 0.f, 0.f, 0.f);
        v.x = 0.5f * v.x * (1.f + erff(v.x * 0.70710678118f));
        v.y = 0.5f * v.y * (1.f + erff(v.y * 0.70710678118f));
        v.z = 0.5f * v.z * (1.f + erff(v.z * 0.70710678118f));
        v.w = 0.5f * v.w * (1.f + erff(v.w * 0.70710678118f));
        split_store(sm, OFF_AHI, OFF_ALO, row, col, v);
        float4 w = __ldg((const float4*)(wg + row * 128 + col));
        split_store(sm, OFF_BHI, OFF_BLO, row, col, w);
    }
    __syncthreads();

    AccTile T;
    mma_tile_compute(T, smb, wid, lane);
    __syncthreads();

    float* Cs = (float*)sm;
    {
        const float* bias = ab + t * 128;
        int wm = wid & 1, wn = wid >> 1;
        int g = lane >> 2, tig = lane & 3;
        float2 bfr[4];
        #pragma unroll
        for (int nt = 0; nt < 4; nt++)
            bfr[nt] = *(const float2*)(bias + wn * 32 + nt * 8 + tig * 2);
        #pragma unroll
        for (int mt = 0; mt < 4; mt++) {
            int r0 = wm * 64 + mt * 16 + g;
            #pragma unroll
            for (int nt = 0; nt < 4; nt++) {
                int col = wn * 32 + nt * 8 + tig * 2;
                Cs[r0 * CSTR + col]           = T.a[mt][nt][0] + bfr[nt].x;
                Cs[r0 * CSTR + col + 1]       = T.a[mt][nt][1] + bfr[nt].y;
                Cs[(r0 + 8) * CSTR + col]     = T.a[mt][nt][2] + bfr[nt].x;
                Cs[(r0 + 8) * CSTR + col + 1] = T.a[mt][nt][3] + bfr[nt].y;
            }
        }
    }
    __syncthreads();

    if (tid < 128) {
        int gr = rbase + tid;
        if (gr < NN) {
            float r[128];
            #pragma unroll
            for (int c = 0; c < 128; c++) r[c] = Cs[tid * CSTR + c];
            float beta = 1.f / (1.f + __expf(-skp[t]));
            const float* xr = x + ((size_t)t * NN + gr) * 128;
            float sum = 0.f, sq = 0.f;
            #pragma unroll
            for (int c4 = 0; c4 < 32; c4++) {
                float4 xv = __ldg((const float4*)(xr + c4 * 4));
                float o0 = fmaxf(beta * r[c4*4+0] + (1.f - beta) * xv.x, 0.f);
                float o1 = fmaxf(beta * r[c4*4+1] + (1.f - beta) * xv.y, 0.f);
                float o2 = fmaxf(beta * r[c4*4+2] + (1.f - beta) * xv.z, 0.f);
                float o3 = fmaxf(beta * r[c4*4+3] + (1.f - beta) * xv.w, 0.f);
                r[c4*4+0] = o0; r[c4*4+1] = o1; r[c4*4+2] = o2; r[c4*4+3] = o3;
                sum += o0 + o1 + o2 + o3;
                sq  += o0*o0 + o1*o1 + o2*o2 + o3*o3;
            }
            float mu  = sum * (1.f / 128.f);
            float var = sq * (1.f / 128.f) - mu * mu;
            float rs  = rsqrtf(var + 1e-5f);
            float* op = out + ((size_t)t * NN + gr) * 128;
            #pragma unroll
            for (int c4 = 0; c4 < 32; c4++) {
                float4 gv = *(const float4*)(lng + c4 * 4);
                float4 bv = *(const float4*)(lnb + c4 * 4);
                float4 o;
                o.x = (r[c4*4+0] - mu) * rs * gv.x + bv.x;
                o.y = (r[c4*4+1] - mu) * rs * gv.y + bv.y;
                o.z = (r[c4*4+2] - mu) * rs * gv.z + bv.z;
                o.w = (r[c4*4+3] - mu) * rs * gv.w + bv.w;
                *(float4*)(op + c4 * 4) = o;
            }
        }
    }
}

// ---------------- launch ----------------
extern "C" void kernel_launch(void* const* d_in, const int* in_sizes, int n_in,
                              void* d_out, int out_size) {
    const float* x   = (const float*)d_in[0];
    const float* kw  = (const float*)d_in[1];
    const float* kb  = (const float*)d_in[2];
    const float* qw  = (const float*)d_in[3];
    const float* qb  = (const float*)d_in[4];
    const float* vw  = (const float*)d_in[5];
    const float* vb  = (const float*)d_in[6];
    const float* aw  = (const float*)d_in[7];
    const float* ab  = (const float*)d_in[8];
    const float* skp = (const float*)d_in[9];
    const float* ar  = (const float*)d_in[10];
    const float* mr  = (const float*)d_in[11];
    const float* pr  = (const float*)d_in[12];
    const float* lng = (const float*)d_in[13];
    const float* lnb = (const float*)d_in[14];
    const int*   ei  = (const int*)d_in[15];
    float* out = (float*)d_out;

    cudaFuncSetAttribute(proj_mma, cudaFuncAttributeMaxDynamicSharedMemorySize, SM_TOTAL);
    cudaFuncSetAttribute(out_mma,  cudaFuncAttributeMaxDynamicSharedMemorySize, SM_TOTAL);

    prep_kernel<<<384, 256>>>(kw, kb, qw, qb, vw, vb, ar, mr, pr);
    csr_zero<<<98, 1024>>>();
    csr_count<<<dim3((NE + 255) / 256, 2), 256>>>(ei);
    csr_scan<<<2, 1024>>>();
    csr_scatter<<<dim3((NE + 255) / 256, 2), 256>>>(ei);
    proj_mma<<<dim3(3, 391, 2), 256, SM_TOTAL>>>(x);
    edge_fused<<<dim3(NN / 8, 2), 256>>>();
    out_mma<<<dim3(391, 2), 256, SM_TOTAL>>>(x, aw, ab, skp, lng, lnb, out);
}

// round 9
// speedup vs baseline: 1.9806x; 1.1277x over previous
#include <cuda_runtime.h>
#include <cuda_bf16.h>
#include <math.h>
#include <stdint.h>

#define NT 2
#define NN 50000
#define NE 500000
#define NI 128
#define NO 128
#define NH 8
#define ND 16

// ---------------- scratch (allocation-free: device globals) ----------------
__device__ __align__(16) float g_Wc [NT*384*NI];
__device__ __align__(16) float g_bc [NT*384];
__device__ __align__(16) float g_q  [NT*NN*NO];
__device__ __align__(16) float g_ke [NT*NN*NO];
__device__ __align__(16) float g_ve [NT*NN*NO];
__device__ __align__(16) float g_agg[NT*NN*NO];
__device__ __align__(16) float g_exc[2ll*NE*NH];     // ex per (relation, csr-pos, head)
__device__ __align__(16) int   g_cnt[2*NN];
__device__ __align__(16) int   g_cur[2*NN];
__device__ __align__(16) int   g_off[2*NN];          // segment base per (relation, node)
__device__                int   g_base[2];            // per-relation allocation cursor
__device__ __align__(16) int   g_csr[2*NE];          // src indices grouped by dst

// ---------------- smem layout for MMA kernels ----------------
#define STRB 272
#define OFF_AHI 0
#define OFF_ALO 34816
#define OFF_BHI 69632
#define OFF_BLO 104448
#define SM_TOTAL 139264
#define CSTR 133

__device__ __forceinline__ uint32_t smem_u32(const void* p) {
    uint32_t a;
    asm("{ .reg .u64 t; cvta.to.shared.u64 t, %1; cvt.u32.u64 %0, t; }" : "=r"(a) : "l"(p));
    return a;
}
__device__ __forceinline__ void ldsm_x4(uint32_t& r0, uint32_t& r1, uint32_t& r2, uint32_t& r3, uint32_t addr) {
    asm volatile("ldmatrix.sync.aligned.m8n8.x4.shared.b16 {%0,%1,%2,%3}, [%4];"
                 : "=r"(r0), "=r"(r1), "=r"(r2), "=r"(r3) : "r"(addr));
}
__device__ __forceinline__ void ldsm_x2(uint32_t& r0, uint32_t& r1, uint32_t addr) {
    asm volatile("ldmatrix.sync.aligned.m8n8.x2.shared.b16 {%0,%1}, [%2];"
                 : "=r"(r0), "=r"(r1) : "r"(addr));
}
__device__ __forceinline__ void mma16816(float& c0, float& c1, float& c2, float& c3,
                                         uint32_t a0, uint32_t a1, uint32_t a2, uint32_t a3,
                                         uint32_t b0, uint32_t b1) {
    asm volatile("mma.sync.aligned.m16n8k16.row.col.f32.bf16.bf16.f32 "
                 "{%0,%1,%2,%3}, {%4,%5,%6,%7}, {%8,%9}, {%0,%1,%2,%3};"
                 : "+f"(c0), "+f"(c1), "+f"(c2), "+f"(c3)
                 : "r"(a0), "r"(a1), "r"(a2), "r"(a3), "r"(b0), "r"(b1));
}

__device__ __forceinline__ void split_store(char* sm, int hi_off, int lo_off, int row, int col, float4 v) {
    __nv_bfloat16 h0 = __float2bfloat16(v.x), h1 = __float2bfloat16(v.y),
                  h2 = __float2bfloat16(v.z), h3 = __float2bfloat16(v.w);
    float l0 = v.x - __bfloat162float(h0), l1 = v.y - __bfloat162float(h1),
          l2 = v.z - __bfloat162float(h2), l3 = v.w - __bfloat162float(h3);
    __nv_bfloat162 ph0; ph0.x = h0; ph0.y = h1;
    __nv_bfloat162 ph1; ph1.x = h2; ph1.y = h3;
    __nv_bfloat162 pl0 = __floats2bfloat162_rn(l0, l1);
    __nv_bfloat162 pl1 = __floats2bfloat162_rn(l2, l3);
    int off = row * STRB + col * 2;
    *reinterpret_cast<uint2*>(sm + hi_off + off) =
        make_uint2(*reinterpret_cast<unsigned*>(&ph0), *reinterpret_cast<unsigned*>(&ph1));
    *reinterpret_cast<uint2*>(sm + lo_off + off) =
        make_uint2(*reinterpret_cast<unsigned*>(&pl0), *reinterpret_cast<unsigned*>(&pl1));
}

struct AccTile { float a[4][4][4]; };

__device__ __forceinline__ void mma_tile_compute(AccTile& T, uint32_t smb, int wid, int lane) {
    int wm = wid & 1, wn = wid >> 1;
    #pragma unroll
    for (int mt = 0; mt < 4; mt++)
        #pragma unroll
        for (int nt = 0; nt < 4; nt++)
            #pragma unroll
            for (int k = 0; k < 4; k++) T.a[mt][nt][k] = 0.f;

    uint32_t a_base[4], b_base[4];
    {
        int arow = wm * 64 + (lane & 15);
        int acol = ((lane >> 4) << 3);
        #pragma unroll
        for (int mt = 0; mt < 4; mt++)
            a_base[mt] = smb + (arow + mt * 16) * STRB + acol * 2;
        int brow = wn * 32 + (lane & 7);
        int bcol = (lane & 8);
        #pragma unroll
        for (int nt = 0; nt < 4; nt++)
            b_base[nt] = smb + (brow + nt * 8) * STRB + bcol * 2;
    }

    const int pa[3] = {OFF_AHI, OFF_AHI, OFF_ALO};
    const int pb[3] = {OFF_BHI, OFF_BLO, OFF_BHI};
    #pragma unroll
    for (int p = 0; p < 3; p++) {
        #pragma unroll
        for (int kt = 0; kt < 8; kt++) {
            uint32_t af[4][4], bf[4][2];
            #pragma unroll
            for (int mt = 0; mt < 4; mt++)
                ldsm_x4(af[mt][0], af[mt][1], af[mt][2], af[mt][3],
                        a_base[mt] + pa[p] + kt * 32);
            #pragma unroll
            for (int nt = 0; nt < 4; nt++)
                ldsm_x2(bf[nt][0], bf[nt][1], b_base[nt] + pb[p] + kt * 32);
            #pragma unroll
            for (int mt = 0; mt < 4; mt++)
                #pragma unroll
                for (int nt = 0; nt < 4; nt++)
                    mma16816(T.a[mt][nt][0], T.a[mt][nt][1], T.a[mt][nt][2], T.a[mt][nt][3],
                             af[mt][0], af[mt][1], af[mt][2], af[mt][3],
                             bf[nt][0], bf[nt][1]);
        }
    }
}

// ---------------- kernel 1: build effective weights ----------------
__global__ void prep_kernel(const float* __restrict__ kw, const float* __restrict__ kb,
                            const float* __restrict__ qw, const float* __restrict__ qb,
                            const float* __restrict__ vw, const float* __restrict__ vb,
                            const float* __restrict__ ar, const float* __restrict__ mr,
                            const float* __restrict__ pr) {
    int gid = blockIdx.x * 256 + threadIdx.x;
    if (gid >= NT * 384 * NI) return;
    int t   = gid / (384 * NI);
    int rem = gid % (384 * NI);
    int row = rem / NI;
    int i   = rem % NI;
    float w, b;
    if (row < 128) {
        w = qw[(t*NO + row)*NI + i];
        b = qb[t*NO + row];
    } else if (row < 256) {
        int r = row - 128, h = r >> 4, j = r & 15;
        float s = pr[t*NH + h] * 0.25f;
        float acc = 0.f, bacc = 0.f;
        #pragma unroll
        for (int d = 0; d < 16; d++) {
            float a = ar[((t*NH + h)*ND + d)*ND + j];
            acc  += kw[(t*NO + h*16 + d)*NI + i] * a;
            bacc += kb[t*NO + h*16 + d] * a;
        }
        w = acc * s; b = bacc * s;
    } else {
        int r = row - 256, h = r >> 4, j = r & 15;
        float acc = 0.f, bacc = 0.f;
        #pragma unroll
        for (int d = 0; d < 16; d++) {
            float m = mr[((t*NH + h)*ND + d)*ND + j];
            acc  += vw[(t*NO + h*16 + d)*NI + i] * m;
            bacc += vb[t*NO + h*16 + d] * m;
        }
        w = acc; b = bacc;
    }
    g_Wc[gid] = w;
    if (i == 0) g_bc[t*384 + row] = b;
}

// ---------------- CSR build ----------------
__global__ void csr_zero() {
    int i = blockIdx.x * 1024 + threadIdx.x;
    if (i < 2 * NN) { g_cnt[i] = 0; g_cur[i] = 0; }
    if (i < 2) g_base[i] = 0;
}

__global__ void csr_count(const int* __restrict__ ei) {
    int e = blockIdx.y;
    int idx = blockIdx.x * 256 + threadIdx.x;
    if (idx >= NE) return;
    int dst = ei[(size_t)e * 2 * NE + NE + idx];
    atomicAdd(&g_cnt[e * NN + dst], 1);
}

// warp-aggregated segment allocation: one global atomic per warp
__global__ void csr_alloc() {
    int e = blockIdx.y;
    int idx = blockIdx.x * 256 + threadIdx.x;
    int lane = threadIdx.x & 31;
    int cnt = (idx < NN) ? g_cnt[e * NN + idx] : 0;
    int incl = cnt;
    #pragma unroll
    for (int d = 1; d < 32; d <<= 1) {
        int v = __shfl_up_sync(0xffffffffu, incl, d);
        if (lane >= d) incl += v;
    }
    int total = __shfl_sync(0xffffffffu, incl, 31);
    int base = 0;
    if (lane == 31) base = atomicAdd(&g_base[e], total);
    base = __shfl_sync(0xffffffffu, base, 31);
    if (idx < NN) g_off[e * NN + idx] = base + incl - cnt;
}

__global__ void csr_scatter(const int* __restrict__ ei) {
    int e = blockIdx.y;
    int idx = blockIdx.x * 256 + threadIdx.x;
    if (idx >= NE) return;
    const int* srcp = ei + (size_t)e * 2 * NE;
    int src = srcp[idx], dst = srcp[NE + idx];
    int pos = atomicAdd(&g_cur[e * NN + dst], 1);
    g_csr[e * NE + g_off[e * NN + dst] + pos] = src;
}

// ---------------- kernel 3: projection GEMM (mma.sync bf16 split) ----------------
__global__ __launch_bounds__(256, 1) void proj_mma(const float* __restrict__ x) {
    extern __shared__ char sm[];
    uint32_t smb = smem_u32(sm);
    int tid = threadIdx.x, wid = tid >> 5, lane = tid & 31;
    int cb = blockIdx.x, rb = blockIdx.y, t = blockIdx.z;
    int rbase = rb * 128;

    const float* xg = x    + (size_t)t * NN * NI;
    const float* wg = g_Wc + ((size_t)t * 384 + cb * 128) * NI;

    #pragma unroll 4
    for (int it = 0; it < 16; it++) {
        int lin = it * 256 + tid;
        int row = lin >> 5, col = (lin & 31) * 4;
        int gr = rbase + row;
        float4 v = (gr < NN) ? __ldg((const float4*)(xg + (size_t)gr * 128 + col))
                             : make_float4(0.f, 0.f, 0.f, 0.f);
        split_store(sm, OFF_AHI, OFF_ALO, row, col, v);
        float4 w = __ldg((const float4*)(wg + row * 128 + col));
        split_store(sm, OFF_BHI, OFF_BLO, row, col, w);
    }
    __syncthreads();

    AccTile T;
    mma_tile_compute(T, smb, wid, lane);

    float* outb = (cb == 0) ? g_q : (cb == 1) ? g_ke : g_ve;
    outb += (size_t)t * NN * NO;
    const float* bias = g_bc + t * 384 + cb * 128;
    int wm = wid & 1, wn = wid >> 1;
    int g = lane >> 2, tig = lane & 3;
    float2 bfr[4];
    #pragma unroll
    for (int nt = 0; nt < 4; nt++)
        bfr[nt] = *(const float2*)(bias + wn * 32 + nt * 8 + tig * 2);
    #pragma unroll
    for (int mt = 0; mt < 4; mt++) {
        int r0 = rbase + wm * 64 + mt * 16 + g;
        #pragma unroll
        for (int nt = 0; nt < 4; nt++) {
            int col = wn * 32 + nt * 8 + tig * 2;
            if (r0 < NN)
                *(float2*)(outb + (size_t)r0 * 128 + col) =
                    make_float2(T.a[mt][nt][0] + bfr[nt].x, T.a[mt][nt][1] + bfr[nt].y);
            if (r0 + 8 < NN)
                *(float2*)(outb + (size_t)(r0 + 8) * 128 + col) =
                    make_float2(T.a[mt][nt][2] + bfr[nt].x, T.a[mt][nt][3] + bfr[nt].y);
        }
    }
}

// ---------------- kernel 4: fused attention + aggregation (warp per dst node) ----------------
__global__ __launch_bounds__(256) void edge_fused() {
    int e  = blockIdx.y, dt = 1 - e;
    int wid = threadIdx.x >> 5, lane = threadIdx.x & 31;
    int node = blockIdx.x * 8 + wid;
    // node < NN guaranteed: grid.x = NN/8 = 6250 exact

    float4 qv = ((const float4*)(g_q + ((size_t)dt * NN + node) * NO))[lane];
    int j0 = g_off[e * NN + node];
    int j1 = j0 + g_cnt[e * NN + node];
    int quad = lane >> 2, ql = lane & 3;

    const int*   csr = g_csr + (size_t)e * NE;
    const float* keb = g_ke + (size_t)e * NN * NO;
    const float* veb = g_ve + (size_t)e * NN * NO;
    float*       exb = g_exc + (size_t)e * NE * NH;

    float den = 0.f;
    for (int j = j0; j < j1; j++) {
        int src = csr[j];
        float4 kv = ((const float4*)(keb + (size_t)src * NO))[lane];
        float d = qv.x * kv.x + qv.y * kv.y + qv.z * kv.z + qv.w * kv.w;
        d += __shfl_xor_sync(0xffffffffu, d, 1);
        d += __shfl_xor_sync(0xffffffffu, d, 2);
        float ex = __expf(d);
        den += ex;
        if (ql == 0) exb[(size_t)j * NH + quad] = ex;
    }
    float inv = 1.f / (den + 1e-16f);

    float4 acc = make_float4(0.f, 0.f, 0.f, 0.f);
    for (int j = j0; j < j1; j++) {
        int src = csr[j];
        float ex = exb[(size_t)j * NH + quad];
        float4 vv = ((const float4*)(veb + (size_t)src * NO))[lane];
        acc.x += vv.x * ex; acc.y += vv.y * ex;
        acc.z += vv.z * ex; acc.w += vv.w * ex;
    }
    acc.x *= inv; acc.y *= inv; acc.z *= inv; acc.w *= inv;
    ((float4*)(g_agg + ((size_t)dt * NN + node) * NO))[lane] = acc;
}

// ---------------- kernel 5: epilogue GEMM + skip + relu + LayerNorm ----------------
__global__ __launch_bounds__(256, 1) void out_mma(const float* __restrict__ x,
                                                  const float* __restrict__ aw,
                                                  const float* __restrict__ ab,
                                                  const float* __restrict__ skp,
                                                  const float* __restrict__ lng,
                                                  const float* __restrict__ lnb,
                                                  float* __restrict__ out) {
    extern __shared__ char sm[];
    uint32_t smb = smem_u32(sm);
    int tid = threadIdx.x, wid = tid >> 5, lane = tid & 31;
    int rb = blockIdx.x, t = blockIdx.y;
    int rbase = rb * 128;

    const float* ag = g_agg + (size_t)t * NN * NO;
    const float* wg = aw    + (size_t)t * NO * NO;

    #pragma unroll 4
    for (int it = 0; it < 16; it++) {
        int lin = it * 256 + tid;
        int row = lin >> 5, col = (lin & 31) * 4;
        int gr = rbase + row;
        float4 v = (gr < NN) ? __ldg((const float4*)(ag + (size_t)gr * 128 + col))
                             : make_float4(0.f, 0.f, 0.f, 0.f);
        v.x = 0.5f * v.x * (1.f + erff(v.x * 0.70710678118f));
        v.y = 0.5f * v.y * (1.f + erff(v.y * 0.70710678118f));
        v.z = 0.5f * v.z * (1.f + erff(v.z * 0.70710678118f));
        v.w = 0.5f * v.w * (1.f + erff(v.w * 0.70710678118f));
        split_store(sm, OFF_AHI, OFF_ALO, row, col, v);
        float4 w = __ldg((const float4*)(wg + row * 128 + col));
        split_store(sm, OFF_BHI, OFF_BLO, row, col, w);
    }
    __syncthreads();

    AccTile T;
    mma_tile_compute(T, smb, wid, lane);
    __syncthreads();

    float* Cs = (float*)sm;
    {
        const float* bias = ab + t * 128;
        int wm = wid & 1, wn = wid >> 1;
        int g = lane >> 2, tig = lane & 3;
        float2 bfr[4];
        #pragma unroll
        for (int nt = 0; nt < 4; nt++)
            bfr[nt] = *(const float2*)(bias + wn * 32 + nt * 8 + tig * 2);
        #pragma unroll
        for (int mt = 0; mt < 4; mt++) {
            int r0 = wm * 64 + mt * 16 + g;
            #pragma unroll
            for (int nt = 0; nt < 4; nt++) {
                int col = wn * 32 + nt * 8 + tig * 2;
                Cs[r0 * CSTR + col]           = T.a[mt][nt][0] + bfr[nt].x;
                Cs[r0 * CSTR + col + 1]       = T.a[mt][nt][1] + bfr[nt].y;
                Cs[(r0 + 8) * CSTR + col]     = T.a[mt][nt][2] + bfr[nt].x;
                Cs[(r0 + 8) * CSTR + col + 1] = T.a[mt][nt][3] + bfr[nt].y;
            }
        }
    }
    __syncthreads();

    if (tid < 128) {
        int gr = rbase + tid;
        if (gr < NN) {
            float r[128];
            #pragma unroll
            for (int c = 0; c < 128; c++) r[c] = Cs[tid * CSTR + c];
            float beta = 1.f / (1.f + __expf(-skp[t]));
            const float* xr = x + ((size_t)t * NN + gr) * 128;
            float sum = 0.f, sq = 0.f;
            #pragma unroll
            for (int c4 = 0; c4 < 32; c4++) {
                float4 xv = __ldg((const float4*)(xr + c4 * 4));
                float o0 = fmaxf(beta * r[c4*4+0] + (1.f - beta) * xv.x, 0.f);
                float o1 = fmaxf(beta * r[c4*4+1] + (1.f - beta) * xv.y, 0.f);
                float o2 = fmaxf(beta * r[c4*4+2] + (1.f - beta) * xv.z, 0.f);
                float o3 = fmaxf(beta * r[c4*4+3] + (1.f - beta) * xv.w, 0.f);
                r[c4*4+0] = o0; r[c4*4+1] = o1; r[c4*4+2] = o2; r[c4*4+3] = o3;
                sum += o0 + o1 + o2 + o3;
                sq  += o0*o0 + o1*o1 + o2*o2 + o3*o3;
            }
            float mu  = sum * (1.f / 128.f);
            float var = sq * (1.f / 128.f) - mu * mu;
            float rs  = rsqrtf(var + 1e-5f);
            float* op = out + ((size_t)t * NN + gr) * 128;
            #pragma unroll
            for (int c4 = 0; c4 < 32; c4++) {
                float4 gv = *(const float4*)(lng + c4 * 4);
                float4 bv = *(const float4*)(lnb + c4 * 4);
                float4 o;
                o.x = (r[c4*4+0] - mu) * rs * gv.x + bv.x;
                o.y = (r[c4*4+1] - mu) * rs * gv.y + bv.y;
                o.z = (r[c4*4+2] - mu) * rs * gv.z + bv.z;
                o.w = (r[c4*4+3] - mu) * rs * gv.w + bv.w;
                *(float4*)(op + c4 * 4) = o;
            }
        }
    }
}

// ---------------- launch ----------------
extern "C" void kernel_launch(void* const* d_in, const int* in_sizes, int n_in,
                              void* d_out, int out_size) {
    const float* x   = (const float*)d_in[0];
    const float* kw  = (const float*)d_in[1];
    const float* kb  = (const float*)d_in[2];
    const float* qw  = (const float*)d_in[3];
    const float* qb  = (const float*)d_in[4];
    const float* vw  = (const float*)d_in[5];
    const float* vb  = (const float*)d_in[6];
    const float* aw  = (const float*)d_in[7];
    const float* ab  = (const float*)d_in[8];
    const float* skp = (const float*)d_in[9];
    const float* ar  = (const float*)d_in[10];
    const float* mr  = (const float*)d_in[11];
    const float* pr  = (const float*)d_in[12];
    const float* lng = (const float*)d_in[13];
    const float* lnb = (const float*)d_in[14];
    const int*   ei  = (const int*)d_in[15];
    float* out = (float*)d_out;

    cudaFuncSetAttribute(proj_mma, cudaFuncAttributeMaxDynamicSharedMemorySize, SM_TOTAL);
    cudaFuncSetAttribute(out_mma,  cudaFuncAttributeMaxDynamicSharedMemorySize, SM_TOTAL);

    prep_kernel<<<384, 256>>>(kw, kb, qw, qb, vw, vb, ar, mr, pr);
    csr_zero<<<98, 1024>>>();
    csr_count<<<dim3((NE + 255) / 256, 2), 256>>>(ei);
    csr_alloc<<<dim3((NN + 255) / 256, 2), 256>>>();
    csr_scatter<<<dim3((NE + 255) / 256, 2), 256>>>(ei);
    proj_mma<<<dim3(3, 391, 2), 256, SM_TOTAL>>>(x);
    edge_fused<<<dim3(NN / 8, 2), 256>>>();
    out_mma<<<dim3(391, 2), 256, SM_TOTAL>>>(x, aw, ab, skp, lng, lnb, out);
}

// round 10
// speedup vs baseline: 2.1103x; 1.0655x over previous
#include <cuda_runtime.h>
#include <cuda_bf16.h>
#include <math.h>
#include <stdint.h>

#define NT 2
#define NN 50000
#define NE 500000
#define NI 128
#define NO 128
#define NH 8
#define ND 16
#define NRB 391          // ceil(NN/128)
#define PROJ_Z 24        // persistent grid depth for proj (3*2*24 = 144 CTAs)
#define OUT_Z 74         // persistent grid width for out (74*2 = 148 CTAs)

// ---------------- scratch (allocation-free: device globals) ----------------
__device__ __align__(16) float g_Wc [NT*384*NI];
__device__ __align__(16) float g_bc [NT*384];
__device__ __align__(16) float g_q  [NT*NN*NO];
__device__ __align__(16) float g_ke [NT*NN*NO];
__device__ __align__(16) float g_ve [NT*NN*NO];
__device__ __align__(16) float g_agg[NT*NN*NO];
__device__ __align__(16) int   g_cnt[2*NN];
__device__ __align__(16) int   g_cur[2*NN];
__device__ __align__(16) int   g_off[2*NN];
__device__                int   g_base[2];
__device__ __align__(16) int   g_csr[2*NE];

// ---------------- smem layout for MMA kernels ----------------
#define STRB 272
#define OFF_AHI 0
#define OFF_ALO 34816
#define OFF_BHI 69632
#define OFF_BLO 104448
#define SM_TOTAL 139264
#define CSTR 133

__device__ __forceinline__ uint32_t smem_u32(const void* p) {
    uint32_t a;
    asm("{ .reg .u64 t; cvta.to.shared.u64 t, %1; cvt.u32.u64 %0, t; }" : "=r"(a) : "l"(p));
    return a;
}
__device__ __forceinline__ void ldsm_x4(uint32_t& r0, uint32_t& r1, uint32_t& r2, uint32_t& r3, uint32_t addr) {
    asm volatile("ldmatrix.sync.aligned.m8n8.x4.shared.b16 {%0,%1,%2,%3}, [%4];"
                 : "=r"(r0), "=r"(r1), "=r"(r2), "=r"(r3) : "r"(addr));
}
__device__ __forceinline__ void ldsm_x2(uint32_t& r0, uint32_t& r1, uint32_t addr) {
    asm volatile("ldmatrix.sync.aligned.m8n8.x2.shared.b16 {%0,%1}, [%2];"
                 : "=r"(r0), "=r"(r1) : "r"(addr));
}
__device__ __forceinline__ void mma16816(float& c0, float& c1, float& c2, float& c3,
                                         uint32_t a0, uint32_t a1, uint32_t a2, uint32_t a3,
                                         uint32_t b0, uint32_t b1) {
    asm volatile("mma.sync.aligned.m16n8k16.row.col.f32.bf16.bf16.f32 "
                 "{%0,%1,%2,%3}, {%4,%5,%6,%7}, {%8,%9}, {%0,%1,%2,%3};"
                 : "+f"(c0), "+f"(c1), "+f"(c2), "+f"(c3)
                 : "r"(a0), "r"(a1), "r"(a2), "r"(a3), "r"(b0), "r"(b1));
}

__device__ __forceinline__ void split_store(char* sm, int hi_off, int lo_off, int row, int col, float4 v) {
    __nv_bfloat16 h0 = __float2bfloat16(v.x), h1 = __float2bfloat16(v.y),
                  h2 = __float2bfloat16(v.z), h3 = __float2bfloat16(v.w);
    float l0 = v.x - __bfloat162float(h0), l1 = v.y - __bfloat162float(h1),
          l2 = v.z - __bfloat162float(h2), l3 = v.w - __bfloat162float(h3);
    __nv_bfloat162 ph0; ph0.x = h0; ph0.y = h1;
    __nv_bfloat162 ph1; ph1.x = h2; ph1.y = h3;
    __nv_bfloat162 pl0 = __floats2bfloat162_rn(l0, l1);
    __nv_bfloat162 pl1 = __floats2bfloat162_rn(l2, l3);
    int off = row * STRB + col * 2;
    *reinterpret_cast<uint2*>(sm + hi_off + off) =
        make_uint2(*reinterpret_cast<unsigned*>(&ph0), *reinterpret_cast<unsigned*>(&ph1));
    *reinterpret_cast<uint2*>(sm + lo_off + off) =
        make_uint2(*reinterpret_cast<unsigned*>(&pl0), *reinterpret_cast<unsigned*>(&pl1));
}

struct AccTile { float a[4][4][4]; };

__device__ __forceinline__ void mma_tile_compute(AccTile& T, uint32_t smb, int wid, int lane) {
    int wm = wid & 1, wn = wid >> 1;
    #pragma unroll
    for (int mt = 0; mt < 4; mt++)
        #pragma unroll
        for (int nt = 0; nt < 4; nt++)
            #pragma unroll
            for (int k = 0; k < 4; k++) T.a[mt][nt][k] = 0.f;

    uint32_t a_base[4], b_base[4];
    {
        int arow = wm * 64 + (lane & 15);
        int acol = ((lane >> 4) << 3);
        #pragma unroll
        for (int mt = 0; mt < 4; mt++)
            a_base[mt] = smb + (arow + mt * 16) * STRB + acol * 2;
        int brow = wn * 32 + (lane & 7);
        int bcol = (lane & 8);
        #pragma unroll
        for (int nt = 0; nt < 4; nt++)
            b_base[nt] = smb + (brow + nt * 8) * STRB + bcol * 2;
    }

    const int pa[3] = {OFF_AHI, OFF_AHI, OFF_ALO};
    const int pb[3] = {OFF_BHI, OFF_BLO, OFF_BHI};
    #pragma unroll
    for (int p = 0; p < 3; p++) {
        #pragma unroll
        for (int kt = 0; kt < 8; kt++) {
            uint32_t af[4][4], bf[4][2];
            #pragma unroll
            for (int mt = 0; mt < 4; mt++)
                ldsm_x4(af[mt][0], af[mt][1], af[mt][2], af[mt][3],
                        a_base[mt] + pa[p] + kt * 32);
            #pragma unroll
            for (int nt = 0; nt < 4; nt++)
                ldsm_x2(bf[nt][0], bf[nt][1], b_base[nt] + pb[p] + kt * 32);
            #pragma unroll
            for (int mt = 0; mt < 4; mt++)
                #pragma unroll
                for (int nt = 0; nt < 4; nt++)
                    mma16816(T.a[mt][nt][0], T.a[mt][nt][1], T.a[mt][nt][2], T.a[mt][nt][3],
                             af[mt][0], af[mt][1], af[mt][2], af[mt][3],
                             bf[nt][0], bf[nt][1]);
        }
    }
}

// ---------------- kernel 1: build effective weights ----------------
__global__ void prep_kernel(const float* __restrict__ kw, const float* __restrict__ kb,
                            const float* __restrict__ qw, const float* __restrict__ qb,
                            const float* __restrict__ vw, const float* __restrict__ vb,
                            const float* __restrict__ ar, const float* __restrict__ mr,
                            const float* __restrict__ pr) {
    int gid = blockIdx.x * 256 + threadIdx.x;
    if (gid >= NT * 384 * NI) return;
    int t   = gid / (384 * NI);
    int rem = gid % (384 * NI);
    int row = rem / NI;
    int i   = rem % NI;
    float w, b;
    if (row < 128) {
        w = qw[(t*NO + row)*NI + i];
        b = qb[t*NO + row];
    } else if (row < 256) {
        int r = row - 128, h = r >> 4, j = r & 15;
        float s = pr[t*NH + h] * 0.25f;
        float acc = 0.f, bacc = 0.f;
        #pragma unroll
        for (int d = 0; d < 16; d++) {
            float a = ar[((t*NH + h)*ND + d)*ND + j];
            acc  += kw[(t*NO + h*16 + d)*NI + i] * a;
            bacc += kb[t*NO + h*16 + d] * a;
        }
        w = acc * s; b = bacc * s;
    } else {
        int r = row - 256, h = r >> 4, j = r & 15;
        float acc = 0.f, bacc = 0.f;
        #pragma unroll
        for (int d = 0; d < 16; d++) {
            float m = mr[((t*NH + h)*ND + d)*ND + j];
            acc  += vw[(t*NO + h*16 + d)*NI + i] * m;
            bacc += vb[t*NO + h*16 + d] * m;
        }
        w = acc; b = bacc;
    }
    g_Wc[gid] = w;
    if (i == 0) g_bc[t*384 + row] = b;
}

// ---------------- CSR build ----------------
__global__ void csr_zero() {
    int i = blockIdx.x * 1024 + threadIdx.x;
    if (i < 2 * NN) { g_cnt[i] = 0; g_cur[i] = 0; }
    if (i < 2) g_base[i] = 0;
}

__global__ void csr_count(const int* __restrict__ ei) {
    int e = blockIdx.y;
    int idx = blockIdx.x * 256 + threadIdx.x;
    if (idx >= NE) return;
    int dst = ei[(size_t)e * 2 * NE + NE + idx];
    atomicAdd(&g_cnt[e * NN + dst], 1);
}

__global__ void csr_alloc() {
    int e = blockIdx.y;
    int idx = blockIdx.x * 256 + threadIdx.x;
    int lane = threadIdx.x & 31;
    int cnt = (idx < NN) ? g_cnt[e * NN + idx] : 0;
    int incl = cnt;
    #pragma unroll
    for (int d = 1; d < 32; d <<= 1) {
        int v = __shfl_up_sync(0xffffffffu, incl, d);
        if (lane >= d) incl += v;
    }
    int total = __shfl_sync(0xffffffffu, incl, 31);
    int base = 0;
    if (lane == 31) base = atomicAdd(&g_base[e], total);
    base = __shfl_sync(0xffffffffu, base, 31);
    if (idx < NN) g_off[e * NN + idx] = base + incl - cnt;
}

__global__ void csr_scatter(const int* __restrict__ ei) {
    int e = blockIdx.y;
    int idx = blockIdx.x * 256 + threadIdx.x;
    if (idx >= NE) return;
    const int* srcp = ei + (size_t)e * 2 * NE;
    int src = srcp[idx], dst = srcp[NE + idx];
    int pos = atomicAdd(&g_cur[e * NN + dst], 1);
    g_csr[e * NE + g_off[e * NN + dst] + pos] = src;
}

// ---------------- kernel 3: persistent projection GEMM ----------------
// grid (3, NT, PROJ_Z): each block owns (cb, t) and strides row-blocks by PROJ_Z.
// B (weight) tile loaded once; A tile register-prefetched across iterations.
__global__ __launch_bounds__(256, 1) void proj_mma(const float* __restrict__ x) {
    extern __shared__ char sm[];
    uint32_t smb = smem_u32(sm);
    int tid = threadIdx.x, wid = tid >> 5, lane = tid & 31;
    int cb = blockIdx.x, t = blockIdx.y;

    const float* xg = x    + (size_t)t * NN * NI;
    const float* wg = g_Wc + ((size_t)t * 384 + cb * 128) * NI;

    // load B tile once
    #pragma unroll 4
    for (int it = 0; it < 16; it++) {
        int lin = it * 256 + tid;
        int row = lin >> 5, col = (lin & 31) * 4;
        float4 w = __ldg((const float4*)(wg + row * 128 + col));
        split_store(sm, OFF_BHI, OFF_BLO, row, col, w);
    }

    float* outb = (cb == 0) ? g_q : (cb == 1) ? g_ke : g_ve;
    outb += (size_t)t * NN * NO;
    const float* bias = g_bc + t * 384 + cb * 128;
    int wm = wid & 1, wn = wid >> 1;
    int g = lane >> 2, tig = lane & 3;
    float2 bfr[4];
    #pragma unroll
    for (int nt = 0; nt < 4; nt++)
        bfr[nt] = *(const float2*)(bias + wn * 32 + nt * 8 + tig * 2);

    // prologue: prefetch first A tile into registers
    int rb = blockIdx.z;
    float4 areg[16];
    {
        int rbase = rb * 128;
        #pragma unroll
        for (int it = 0; it < 16; it++) {
            int lin = it * 256 + tid;
            int row = lin >> 5, col = (lin & 31) * 4;
            int gr = rbase + row;
            areg[it] = (gr < NN) ? __ldg((const float4*)(xg + (size_t)gr * 128 + col))
                                 : make_float4(0.f, 0.f, 0.f, 0.f);
        }
    }

    for (; rb < NRB; rb += PROJ_Z) {
        int rbase = rb * 128;
        __syncthreads();           // previous compute done reading A smem
        #pragma unroll
        for (int it = 0; it < 16; it++) {
            int lin = it * 256 + tid;
            int row = lin >> 5, col = (lin & 31) * 4;
            split_store(sm, OFF_AHI, OFF_ALO, row, col, areg[it]);
        }
        __syncthreads();

        // prefetch next tile (overlaps with MMA below)
        int rbn = rb + PROJ_Z;
        if (rbn < NRB) {
            int nbase = rbn * 128;
            #pragma unroll
            for (int it = 0; it < 16; it++) {
                int lin = it * 256 + tid;
                int row = lin >> 5, col = (lin & 31) * 4;
                int gr = nbase + row;
                areg[it] = (gr < NN) ? __ldg((const float4*)(xg + (size_t)gr * 128 + col))
                                     : make_float4(0.f, 0.f, 0.f, 0.f);
            }
        }

        AccTile T;
        mma_tile_compute(T, smb, wid, lane);

        #pragma unroll
        for (int mt = 0; mt < 4; mt++) {
            int r0 = rbase + wm * 64 + mt * 16 + g;
            #pragma unroll
            for (int nt = 0; nt < 4; nt++) {
                int col = wn * 32 + nt * 8 + tig * 2;
                if (r0 < NN)
                    *(float2*)(outb + (size_t)r0 * 128 + col) =
                        make_float2(T.a[mt][nt][0] + bfr[nt].x, T.a[mt][nt][1] + bfr[nt].y);
                if (r0 + 8 < NN)
                    *(float2*)(outb + (size_t)(r0 + 8) * 128 + col) =
                        make_float2(T.a[mt][nt][2] + bfr[nt].x, T.a[mt][nt][3] + bfr[nt].y);
            }
        }
    }
}

// ---------------- kernel 4: fused attention + aggregation (single pass) ----------------
__global__ __launch_bounds__(256) void edge_fused() {
    int e  = blockIdx.y, dt = 1 - e;
    int wid = threadIdx.x >> 5, lane = threadIdx.x & 31;
    int node = blockIdx.x * 8 + wid;   // grid.x = NN/8 exact

    float4 qv = ((const float4*)(g_q + ((size_t)dt * NN + node) * NO))[lane];
    int j0 = g_off[e * NN + node];
    int j1 = j0 + g_cnt[e * NN + node];

    const int*   csr = g_csr + (size_t)e * NE;
    const float* keb = g_ke + (size_t)e * NN * NO;
    const float* veb = g_ve + (size_t)e * NN * NO;

    float den = 0.f;
    float4 acc = make_float4(0.f, 0.f, 0.f, 0.f);
    #pragma unroll 2
    for (int j = j0; j < j1; j++) {
        int src = csr[j];
        float4 kv = ((const float4*)(keb + (size_t)src * NO))[lane];
        float4 vv = ((const float4*)(veb + (size_t)src * NO))[lane];
        float d = qv.x * kv.x + qv.y * kv.y + qv.z * kv.z + qv.w * kv.w;
        d += __shfl_xor_sync(0xffffffffu, d, 1);
        d += __shfl_xor_sync(0xffffffffu, d, 2);
        float ex = __expf(d);
        den += ex;
        acc.x += vv.x * ex; acc.y += vv.y * ex;
        acc.z += vv.z * ex; acc.w += vv.w * ex;
    }
    float inv = 1.f / (den + 1e-16f);
    acc.x *= inv; acc.y *= inv; acc.z *= inv; acc.w *= inv;
    ((float4*)(g_agg + ((size_t)dt * NN + node) * NO))[lane] = acc;
}

// ---------------- kernel 5: persistent epilogue GEMM + skip + relu + LayerNorm ----------------
// grid (OUT_Z, NT): B (aw) tile loaded once per block; strides row-blocks by OUT_Z.
__global__ __launch_bounds__(256, 1) void out_mma(const float* __restrict__ x,
                                                  const float* __restrict__ aw,
                                                  const float* __restrict__ ab,
                                                  const float* __restrict__ skp,
                                                  const float* __restrict__ lng,
                                                  const float* __restrict__ lnb,
                                                  float* __restrict__ out) {
    extern __shared__ char sm[];
    uint32_t smb = smem_u32(sm);
    int tid = threadIdx.x, wid = tid >> 5, lane = tid & 31;
    int t = blockIdx.y;

    const float* ag = g_agg + (size_t)t * NN * NO;
    const float* wg = aw    + (size_t)t * NO * NO;

    // load B (aw) tile once
    #pragma unroll 4
    for (int it = 0; it < 16; it++) {
        int lin = it * 256 + tid;
        int row = lin >> 5, col = (lin & 31) * 4;
        float4 w = __ldg((const float4*)(wg + row * 128 + col));
        split_store(sm, OFF_BHI, OFF_BLO, row, col, w);
    }

    const float* bias = ab + t * 128;
    int wm = wid & 1, wn = wid >> 1;
    int g = lane >> 2, tig = lane & 3;
    float2 bfr[4];
    #pragma unroll
    for (int nt = 0; nt < 4; nt++)
        bfr[nt] = *(const float2*)(bias + wn * 32 + nt * 8 + tig * 2);
    float beta = 1.f / (1.f + __expf(-skp[t]));

    float* Cs = (float*)sm;   // [128][CSTR], overlaps A-tile region only

    for (int rb = blockIdx.x; rb < NRB; rb += OUT_Z) {
        int rbase = rb * 128;
        __syncthreads();       // prior epilogue finished reading Cs / A smem free
        #pragma unroll 4
        for (int it = 0; it < 16; it++) {
            int lin = it * 256 + tid;
            int row = lin >> 5, col = (lin & 31) * 4;
            int gr = rbase + row;
            float4 v = (gr < NN) ? __ldg((const float4*)(ag + (size_t)gr * 128 + col))
                                 : make_float4(0.f, 0.f, 0.f, 0.f);
            v.x = 0.5f * v.x * (1.f + erff(v.x * 0.70710678118f));
            v.y = 0.5f * v.y * (1.f + erff(v.y * 0.70710678118f));
            v.z = 0.5f * v.z * (1.f + erff(v.z * 0.70710678118f));
            v.w = 0.5f * v.w * (1.f + erff(v.w * 0.70710678118f));
            split_store(sm, OFF_AHI, OFF_ALO, row, col, v);
        }
        __syncthreads();

        AccTile T;
        mma_tile_compute(T, smb, wid, lane);
        __syncthreads();       // all warps done reading A smem; reuse as C

        #pragma unroll
        for (int mt = 0; mt < 4; mt++) {
            int r0 = wm * 64 + mt * 16 + g;
            #pragma unroll
            for (int nt = 0; nt < 4; nt++) {
                int col = wn * 32 + nt * 8 + tig * 2;
                Cs[r0 * CSTR + col]           = T.a[mt][nt][0] + bfr[nt].x;
                Cs[r0 * CSTR + col + 1]       = T.a[mt][nt][1] + bfr[nt].y;
                Cs[(r0 + 8) * CSTR + col]     = T.a[mt][nt][2] + bfr[nt].x;
                Cs[(r0 + 8) * CSTR + col + 1] = T.a[mt][nt][3] + bfr[nt].y;
            }
        }
        __syncthreads();

        if (tid < 128) {
            int gr = rbase + tid;
            if (gr < NN) {
                const float* xr = x + ((size_t)t * NN + gr) * 128;
                float sum = 0.f, sq = 0.f;
                #pragma unroll
                for (int c4 = 0; c4 < 32; c4++) {
                    float4 xv = __ldg((const float4*)(xr + c4 * 4));
                    float o0 = fmaxf(beta * Cs[tid * CSTR + c4*4+0] + (1.f - beta) * xv.x, 0.f);
                    float o1 = fmaxf(beta * Cs[tid * CSTR + c4*4+1] + (1.f - beta) * xv.y, 0.f);
                    float o2 = fmaxf(beta * Cs[tid * CSTR + c4*4+2] + (1.f - beta) * xv.z, 0.f);
                    float o3 = fmaxf(beta * Cs[tid * CSTR + c4*4+3] + (1.f - beta) * xv.w, 0.f);
                    Cs[tid * CSTR + c4*4+0] = o0; Cs[tid * CSTR + c4*4+1] = o1;
                    Cs[tid * CSTR + c4*4+2] = o2; Cs[tid * CSTR + c4*4+3] = o3;
                    sum += o0 + o1 + o2 + o3;
                    sq  += o0*o0 + o1*o1 + o2*o2 + o3*o3;
                }
                float mu  = sum * (1.f / 128.f);
                float var = sq * (1.f / 128.f) - mu * mu;
                float rs  = rsqrtf(var + 1e-5f);
                float* op = out + ((size_t)t * NN + gr) * 128;
                #pragma unroll
                for (int c4 = 0; c4 < 32; c4++) {
                    float4 gv = *(const float4*)(lng + c4 * 4);
                    float4 bv = *(const float4*)(lnb + c4 * 4);
                    float4 o;
                    o.x = (Cs[tid * CSTR + c4*4+0] - mu) * rs * gv.x + bv.x;
                    o.y = (Cs[tid * CSTR + c4*4+1] - mu) * rs * gv.y + bv.y;
                    o.z = (Cs[tid * CSTR + c4*4+2] - mu) * rs * gv.z + bv.z;
                    o.w = (Cs[tid * CSTR + c4*4+3] - mu) * rs * gv.w + bv.w;
                    *(float4*)(op + c4 * 4) = o;
                }
            }
        }
    }
}

// ---------------- launch ----------------
extern "C" void kernel_launch(void* const* d_in, const int* in_sizes, int n_in,
                              void* d_out, int out_size) {
    const float* x   = (const float*)d_in[0];
    const float* kw  = (const float*)d_in[1];
    const float* kb  = (const float*)d_in[2];
    const float* qw  = (const float*)d_in[3];
    const float* qb  = (const float*)d_in[4];
    const float* vw  = (const float*)d_in[5];
    const float* vb  = (const float*)d_in[6];
    const float* aw  = (const float*)d_in[7];
    const float* ab  = (const float*)d_in[8];
    const float* skp = (const float*)d_in[9];
    const float* ar  = (const float*)d_in[10];
    const float* mr  = (const float*)d_in[11];
    const float* pr  = (const float*)d_in[12];
    const float* lng = (const float*)d_in[13];
    const float* lnb = (const float*)d_in[14];
    const int*   ei  = (const int*)d_in[15];
    float* out = (float*)d_out;

    cudaFuncSetAttribute(proj_mma, cudaFuncAttributeMaxDynamicSharedMemorySize, SM_TOTAL);
    cudaFuncSetAttribute(out_mma,  cudaFuncAttributeMaxDynamicSharedMemorySize, SM_TOTAL);

    prep_kernel<<<384, 256>>>(kw, kb, qw, qb, vw, vb, ar, mr, pr);
    csr_zero<<<98, 1024>>>();
    csr_count<<<dim3((NE + 255) / 256, 2), 256>>>(ei);
    csr_alloc<<<dim3((NN + 255) / 256, 2), 256>>>();
    csr_scatter<<<dim3((NE + 255) / 256, 2), 256>>>(ei);
    proj_mma<<<dim3(3, NT, PROJ_Z), 256, SM_TOTAL>>>(x);
    edge_fused<<<dim3(NN / 8, 2), 256>>>();
    out_mma<<<dim3(OUT_Z, NT), 256, SM_TOTAL>>>(x, aw, ab, skp, lng, lnb, out);
}